// round 2
// baseline (speedup 1.0000x reference)
#include <cuda_runtime.h>
#include <cuda_bf16.h>
#include <cstdint>

// Problem dims (fixed by reference):
//   S=4, B=512 -> M = S*B = 2048 state rows
//   D=256 (state dim), H=1024 (hidden), T=50 time points -> 49 RK4 steps
#define MROWS 2048
#define DDIM  256
#define HDIM  1024
#define TPTS  50
#define NSTEPS (TPTS - 1)

// -------------------- device scratch (no allocations allowed) --------------------
__device__ float g_y   [MROWS * DDIM];
__device__ float g_ytmp[MROWS * DDIM];
__device__ float g_h1  [MROWS * HDIM];
__device__ float g_h2  [MROWS * HDIM];
__device__ float g_k1  [MROWS * DDIM];
__device__ float g_k2  [MROWS * DDIM];
__device__ float g_k3  [MROWS * DDIM];
__device__ float g_k4  [MROWS * DDIM];

// -------------------- tiled GEMM with bias + optional tanh --------------------
// C[M,N] = act(A[M,K] @ W[K,N] + bias[N])
// grid = (N/BN, M/BM), 256 threads.
template<int BM, int BN, int BK, int TM, int TN, int ACT>
__global__ __launch_bounds__(256)
void gemm_bias_act(const float* __restrict__ A,
                   const float* __restrict__ W,
                   const float* __restrict__ bias,
                   float* __restrict__ C,
                   int N, int K)
{
    constexpr int THREADS = (BM / TM) * (BN / TN);
    static_assert(THREADS == 256, "thread count");
    constexpr int AVEC = (BM * BK) / (4 * THREADS);   // float4 loads per thread for A tile
    constexpr int BVEC = (BN * BK) / (4 * THREADS);   // float4 loads per thread for B tile

    __shared__ float As[BK][BM];
    __shared__ float Bs[BK][BN];

    const int tid = threadIdx.x;
    const int tx  = tid % (BN / TN);
    const int ty  = tid / (BN / TN);
    const int rowBase = blockIdx.y * BM;
    const int colBase = blockIdx.x * BN;

    float acc[TM][TN];
    #pragma unroll
    for (int i = 0; i < TM; i++)
        #pragma unroll
        for (int j = 0; j < TN; j++)
            acc[i][j] = 0.0f;

    for (int k0 = 0; k0 < K; k0 += BK) {
        // Load A tile (row-major [BM x BK]) -> As transposed [BK][BM]
        #pragma unroll
        for (int v = 0; v < AVEC; v++) {
            int idx = tid + v * THREADS;          // one float4 each
            int r   = idx / (BK / 4);
            int kq  = idx % (BK / 4);
            float4 a = *reinterpret_cast<const float4*>(
                &A[(size_t)(rowBase + r) * K + k0 + kq * 4]);
            As[kq * 4 + 0][r] = a.x;
            As[kq * 4 + 1][r] = a.y;
            As[kq * 4 + 2][r] = a.z;
            As[kq * 4 + 3][r] = a.w;
        }
        // Load B tile (row-major [BK x BN]) -> Bs [BK][BN]
        #pragma unroll
        for (int v = 0; v < BVEC; v++) {
            int idx = tid + v * THREADS;
            int kr  = idx / (BN / 4);
            int nq  = idx % (BN / 4);
            *reinterpret_cast<float4*>(&Bs[kr][nq * 4]) =
                *reinterpret_cast<const float4*>(
                    &W[(size_t)(k0 + kr) * N + colBase + nq * 4]);
        }
        __syncthreads();

        #pragma unroll
        for (int kk = 0; kk < BK; kk++) {
            float ra[TM], rb[TN];
            #pragma unroll
            for (int i = 0; i < TM; i++) ra[i] = As[kk][ty * TM + i];
            #pragma unroll
            for (int j = 0; j < TN; j++) rb[j] = Bs[kk][tx * TN + j];
            #pragma unroll
            for (int i = 0; i < TM; i++)
                #pragma unroll
                for (int j = 0; j < TN; j++)
                    acc[i][j] = fmaf(ra[i], rb[j], acc[i][j]);
        }
        __syncthreads();
    }

    // Epilogue: bias + optional tanh, vectorized stores
    #pragma unroll
    for (int i = 0; i < TM; i++) {
        const int row = rowBase + ty * TM + i;
        #pragma unroll
        for (int j = 0; j < TN; j += 4) {
            const int col = colBase + tx * TN + j;
            float4 o;
            float v0 = acc[i][j + 0] + bias[col + 0];
            float v1 = acc[i][j + 1] + bias[col + 1];
            float v2 = acc[i][j + 2] + bias[col + 2];
            float v3 = acc[i][j + 3] + bias[col + 3];
            if (ACT) {
                v0 = tanhf(v0); v1 = tanhf(v1); v2 = tanhf(v2); v3 = tanhf(v3);
            }
            o.x = v0; o.y = v1; o.z = v2; o.w = v3;
            *reinterpret_cast<float4*>(&C[(size_t)row * N + col]) = o;
        }
    }
}

// -------------------- elementwise kernels --------------------
// ytmp = y + coef*dt * k       (dt read from device t[] -> graph-capturable)
__global__ void axpy_kernel(float* __restrict__ out,
                            const float* __restrict__ y,
                            const float* __restrict__ k,
                            const float* __restrict__ t,
                            int step, float coef)
{
    const int i = blockIdx.x * blockDim.x + threadIdx.x;   // float4 index
    const float c = coef * (t[step + 1] - t[step]);
    float4 yv = reinterpret_cast<const float4*>(y)[i];
    float4 kv = reinterpret_cast<const float4*>(k)[i];
    float4 o;
    o.x = fmaf(c, kv.x, yv.x);
    o.y = fmaf(c, kv.y, yv.y);
    o.z = fmaf(c, kv.z, yv.z);
    o.w = fmaf(c, kv.w, yv.w);
    reinterpret_cast<float4*>(out)[i] = o;
}

// y = y + dt/6*(k1 + 2k2 + 2k3 + k4); also writes the new state into the
// output tensor pred_y[S,B,T,D] at time index (step+1).
__global__ void rk4_final_kernel(float* __restrict__ y,
                                 const float* __restrict__ k1,
                                 const float* __restrict__ k2,
                                 const float* __restrict__ k3,
                                 const float* __restrict__ k4,
                                 const float* __restrict__ t,
                                 int step,
                                 float* __restrict__ out)
{
    const int i = blockIdx.x * blockDim.x + threadIdx.x;   // float4 index
    const float s = (t[step + 1] - t[step]) * (1.0f / 6.0f);
    float4 yv = reinterpret_cast<const float4*>(y)[i];
    float4 v1 = reinterpret_cast<const float4*>(k1)[i];
    float4 v2 = reinterpret_cast<const float4*>(k2)[i];
    float4 v3 = reinterpret_cast<const float4*>(k3)[i];
    float4 v4 = reinterpret_cast<const float4*>(k4)[i];
    float4 o;
    o.x = yv.x + s * (v1.x + 2.0f * v2.x + 2.0f * v3.x + v4.x);
    o.y = yv.y + s * (v1.y + 2.0f * v2.y + 2.0f * v3.y + v4.y);
    o.z = yv.z + s * (v1.z + 2.0f * v2.z + 2.0f * v3.z + v4.z);
    o.w = yv.w + s * (v1.w + 2.0f * v2.w + 2.0f * v3.w + v4.w);
    reinterpret_cast<float4*>(y)[i] = o;

    const int e   = i * 4;            // element index into [row, col] with col-dim 256
    const int row = e / DDIM;
    const int col = e % DDIM;
    *reinterpret_cast<float4*>(&out[((size_t)row * TPTS + (step + 1)) * DDIM + col]) = o;
}

// y = first_point; pred_y[:, :, 0, :] = first_point; zero any tail (reg_state).
__global__ void init_kernel(const float* __restrict__ fp,
                            float* __restrict__ y,
                            float* __restrict__ out,
                            int out_size)
{
    const int i = blockIdx.x * blockDim.x + threadIdx.x;   // float4 index
    float4 v = reinterpret_cast<const float4*>(fp)[i];
    reinterpret_cast<float4*>(y)[i] = v;
    const int e   = i * 4;
    const int row = e / DDIM;
    const int col = e % DDIM;
    *reinterpret_cast<float4*>(&out[(size_t)row * TPTS * DDIM + col]) = v;

    // reg_state (or any trailing elements beyond pred_y): zero them
    if (i == 0) {
        const int base = MROWS * TPTS * DDIM;
        for (int z = base; z < out_size; z++) out[z] = 0.0f;
    }
}

// -------------------- launch --------------------
extern "C" void kernel_launch(void* const* d_in, const int* in_sizes, int n_in,
                              void* d_out, int out_size)
{
    const float* fp = (const float*)d_in[0];   // first_point [S,B,D]
    const float* t  = (const float*)d_in[1];   // time_steps  [T]
    const float* W1 = (const float*)d_in[2];   // [D,H]
    const float* b1 = (const float*)d_in[3];   // [H]
    const float* W2 = (const float*)d_in[4];   // [H,H]
    const float* b2 = (const float*)d_in[5];   // [H]
    const float* W3 = (const float*)d_in[6];   // [H,D]
    const float* b3 = (const float*)d_in[7];   // [D]
    float* out = (float*)d_out;

    float *y, *ytmp, *h1, *h2, *k1, *k2, *k3, *k4;
    cudaGetSymbolAddress((void**)&y,    g_y);
    cudaGetSymbolAddress((void**)&ytmp, g_ytmp);
    cudaGetSymbolAddress((void**)&h1,   g_h1);
    cudaGetSymbolAddress((void**)&h2,   g_h2);
    cudaGetSymbolAddress((void**)&k1,   g_k1);
    cudaGetSymbolAddress((void**)&k2,   g_k2);
    cudaGetSymbolAddress((void**)&k3,   g_k3);
    cudaGetSymbolAddress((void**)&k4,   g_k4);

    const int NV4 = (MROWS * DDIM) / 4;        // 131072 float4s
    const dim3 ew_grid(NV4 / 256);

    init_kernel<<<ew_grid, 256>>>(fp, y, out, out_size);

    // f(x) -> kout : three GEMMs
    auto feval = [&](const float* xin, float* kout) {
        // h1 = tanh(x @ W1 + b1)   [2048,256]x[256,1024]
        gemm_bias_act<128, 128, 16, 8, 8, 1>
            <<<dim3(HDIM / 128, MROWS / 128), 256>>>(xin, W1, b1, h1, HDIM, DDIM);
        // h2 = tanh(h1 @ W2 + b2)  [2048,1024]x[1024,1024]
        gemm_bias_act<128, 128, 16, 8, 8, 1>
            <<<dim3(HDIM / 128, MROWS / 128), 256>>>(h1, W2, b2, h2, HDIM, HDIM);
        // k  = h2 @ W3 + b3        [2048,1024]x[1024,256]  (more CTAs: 64x64 tiles)
        gemm_bias_act<64, 64, 16, 4, 4, 0>
            <<<dim3(DDIM / 64, MROWS / 64), 256>>>(h2, W3, b3, kout, DDIM, HDIM);
    };

    for (int s = 0; s < NSTEPS; s++) {
        feval(y, k1);
        axpy_kernel<<<ew_grid, 256>>>(ytmp, y, k1, t, s, 0.5f);
        feval(ytmp, k2);
        axpy_kernel<<<ew_grid, 256>>>(ytmp, y, k2, t, s, 0.5f);
        feval(ytmp, k3);
        axpy_kernel<<<ew_grid, 256>>>(ytmp, y, k3, t, s, 1.0f);
        feval(ytmp, k4);
        rk4_final_kernel<<<ew_grid, 256>>>(y, k1, k2, k3, k4, t, s, out);
    }
}

// round 4
// speedup vs baseline: 2.9144x; 2.9144x over previous
#include <cuda_runtime.h>
#include <cuda_bf16.h>
#include <cstdint>

// Problem dims: S=4, B=512 -> M=2048; D=256; H=1024; T=50 -> 49 RK4 steps
#define MROWS 2048
#define DDIM  256
#define HDIM  1024
#define TPTS  50
#define NSTEPS (TPTS - 1)

// ==================== device scratch ====================
__device__ float g_y [MROWS * DDIM];
__device__ float g_k1[MROWS * DDIM];
__device__ float g_k2[MROWS * DDIM];
__device__ float g_k3[MROWS * DDIM];
__device__ float g_k4[MROWS * DDIM];
// bf16 hi/lo splits of activations
__device__ __nv_bfloat16 g_yh [MROWS * DDIM];
__device__ __nv_bfloat16 g_yl [MROWS * DDIM];
__device__ __nv_bfloat16 g_yth[MROWS * DDIM];
__device__ __nv_bfloat16 g_ytl[MROWS * DDIM];
__device__ __nv_bfloat16 g_h1h[MROWS * HDIM];
__device__ __nv_bfloat16 g_h1l[MROWS * HDIM];
__device__ __nv_bfloat16 g_h2h[MROWS * HDIM];
__device__ __nv_bfloat16 g_h2l[MROWS * HDIM];
// transposed + split weights: Wt[N][K]
__device__ __nv_bfloat16 g_w1h[HDIM * DDIM];
__device__ __nv_bfloat16 g_w1l[HDIM * DDIM];
__device__ __nv_bfloat16 g_w2h[HDIM * HDIM];
__device__ __nv_bfloat16 g_w2l[HDIM * HDIM];
__device__ __nv_bfloat16 g_w3h[DDIM * HDIM];
__device__ __nv_bfloat16 g_w3l[DDIM * HDIM];

__device__ __forceinline__ void split_bf16(float x, __nv_bfloat16& h, __nv_bfloat16& l) {
    h = __float2bfloat16(x);
    l = __float2bfloat16(x - __bfloat162float(h));
}

__device__ __forceinline__ uint32_t smem_u32(const void* p) {
    uint32_t a;
    asm("{ .reg .u64 t; cvta.to.shared.u64 t, %1; cvt.u32.u64 %0, t; }" : "=r"(a) : "l"(p));
    return a;
}
__device__ __forceinline__ void cp_async16(uint32_t dst, const void* src) {
    asm volatile("cp.async.cg.shared.global [%0], [%1], 16;" :: "r"(dst), "l"(src) : "memory");
}
__device__ __forceinline__ void cp_commit() {
    asm volatile("cp.async.commit_group;" ::: "memory");
}
template<int N>
__device__ __forceinline__ void cp_wait() {
    asm volatile("cp.async.wait_group %0;" :: "n"(N) : "memory");
}
__device__ __forceinline__ void ldsm_x4(uint32_t& r0, uint32_t& r1, uint32_t& r2, uint32_t& r3,
                                        uint32_t addr) {
    asm volatile("ldmatrix.sync.aligned.m8n8.x4.shared.b16 {%0,%1,%2,%3}, [%4];"
                 : "=r"(r0), "=r"(r1), "=r"(r2), "=r"(r3) : "r"(addr));
}
__device__ __forceinline__ void mma_bf16(float* c, uint32_t a0, uint32_t a1, uint32_t a2,
                                         uint32_t a3, uint32_t b0, uint32_t b1) {
    asm volatile("mma.sync.aligned.m16n8k16.row.col.f32.bf16.bf16.f32 "
                 "{%0,%1,%2,%3}, {%4,%5,%6,%7}, {%8,%9}, {%0,%1,%2,%3};"
                 : "+f"(c[0]), "+f"(c[1]), "+f"(c[2]), "+f"(c[3])
                 : "r"(a0), "r"(a1), "r"(a2), "r"(a3), "r"(b0), "r"(b1));
}

// ==================== weight transpose + split ====================
__global__ void wsplit_kernel(const float* __restrict__ W, __nv_bfloat16* __restrict__ Th,
                              __nv_bfloat16* __restrict__ Tl, int K, int N) {
    int i = blockIdx.x * blockDim.x + threadIdx.x;
    if (i >= K * N) return;
    int k = i / N, n = i % N;
    __nv_bfloat16 h, l;
    split_bf16(W[i], h, l);
    Th[(size_t)n * K + k] = h;
    Tl[(size_t)n * K + k] = l;
}

// ==================== mma.sync bf16 split-3 GEMM ====================
// C[M,N] = act(A[M,K] @ Wt[N,K]^T + bias)
// A hi/lo: bf16 [M,K]; B = Wt hi/lo: bf16 [N,K]. K-chunks of 64, double-buffered cp.async.
// SMEM tile rows padded to 144B (64 bf16 + 8) for conflict-free ldmatrix.
#define ROWB 144

template<int BM, int BN, int ACT>
__global__ __launch_bounds__(256)
void gemm_mma(const __nv_bfloat16* __restrict__ Ah, const __nv_bfloat16* __restrict__ Al,
              const __nv_bfloat16* __restrict__ Bh, const __nv_bfloat16* __restrict__ Bl,
              const float* __restrict__ bias,
              __nv_bfloat16* __restrict__ Ch, __nv_bfloat16* __restrict__ Cl,
              float* __restrict__ Cf, int N, int K)
{
    constexpr int WR = BM / 32;           // warps along M
    constexpr int WC = 8 / WR;            // warps along N
    constexpr int WN = BN / WC;           // n span per warp
    constexpr int NT = WN / 8;            // n8 tiles per warp
    constexpr int BUF = (2 * BM + 2 * BN) * ROWB;   // bytes per pipeline stage
    static_assert(WR * WC == 8, "warp layout");

    extern __shared__ char smem[];
    const uint32_t sbase = smem_u32(smem);

    const int tid = threadIdx.x, wid = tid >> 5, lane = tid & 31;
    const int wm = wid % WR, wn = wid / WR;
    const int rowBase = blockIdx.y * BM;
    const int colBase = blockIdx.x * BN;

    // tile offsets within a stage
    const uint32_t offAh = 0;
    const uint32_t offAl = (uint32_t)BM * ROWB;
    const uint32_t offBh = (uint32_t)2 * BM * ROWB;
    const uint32_t offBl = (uint32_t)(2 * BM + BN) * ROWB;

    const int nchunks = K >> 6;

    // ---- async load of one chunk into stage b ----
    auto load_chunk = [&](int c, int b) {
        const uint32_t stage = sbase + (uint32_t)b * BUF;
        const int kbase = c << 6;
        constexpr int AUNITS = BM * 8;        // 16B units per A tile
        constexpr int BUNITS = BN * 8;
        #pragma unroll
        for (int u = 0; u < AUNITS / 256; u++) {
            int idx = tid + u * 256;
            int r = idx >> 3, q = idx & 7;
            size_t g = (size_t)(rowBase + r) * K + kbase + q * 8;
            uint32_t d = (uint32_t)(r * ROWB + q * 16);
            cp_async16(stage + offAh + d, Ah + g);
            cp_async16(stage + offAl + d, Al + g);
        }
        #pragma unroll
        for (int u = 0; u < BUNITS / 256; u++) {
            int idx = tid + u * 256;
            int r = idx >> 3, q = idx & 7;
            size_t g = (size_t)(colBase + r) * K + kbase + q * 8;
            uint32_t d = (uint32_t)(r * ROWB + q * 16);
            cp_async16(stage + offBh + d, Bh + g);
            cp_async16(stage + offBl + d, Bl + g);
        }
        cp_commit();
    };

    float acc[2][NT][4];
    #pragma unroll
    for (int mt = 0; mt < 2; mt++)
        #pragma unroll
        for (int nt = 0; nt < NT; nt++)
            #pragma unroll
            for (int j = 0; j < 4; j++)
                acc[mt][nt][j] = 0.0f;

    // per-lane ldmatrix address components
    const int aRow = wm * 32 + (lane & 15);          // + mt*16
    const int aByte = (lane & 16);                   // + ks*32
    const int bRow = wn * WN + ((lane & 16) >> 1) + (lane & 7);   // + nt2*16
    const int bByte = ((lane & 8) << 1);             // + ks*32

    load_chunk(0, 0);

    for (int c = 0; c < nchunks; c++) {
        const int b = c & 1;
        if (c + 1 < nchunks) {
            load_chunk(c + 1, b ^ 1);
            cp_wait<1>();
        } else {
            cp_wait<0>();
        }
        __syncthreads();

        const uint32_t stage = sbase + (uint32_t)b * BUF;
        #pragma unroll
        for (int ks = 0; ks < 4; ks++) {
            uint32_t ah[2][4], al[2][4];
            #pragma unroll
            for (int mt = 0; mt < 2; mt++) {
                uint32_t ad = stage + (uint32_t)((aRow + mt * 16) * ROWB + ks * 32 + aByte);
                ldsm_x4(ah[mt][0], ah[mt][1], ah[mt][2], ah[mt][3], ad + offAh);
                ldsm_x4(al[mt][0], al[mt][1], al[mt][2], al[mt][3], ad + offAl);
            }
            uint32_t bh[NT][2], bl[NT][2];
            #pragma unroll
            for (int nt2 = 0; nt2 < NT / 2; nt2++) {
                uint32_t bd = stage + (uint32_t)((bRow + nt2 * 16) * ROWB + ks * 32 + bByte);
                ldsm_x4(bh[nt2 * 2][0], bh[nt2 * 2][1], bh[nt2 * 2 + 1][0], bh[nt2 * 2 + 1][1],
                        bd + offBh);
                ldsm_x4(bl[nt2 * 2][0], bl[nt2 * 2][1], bl[nt2 * 2 + 1][0], bl[nt2 * 2 + 1][1],
                        bd + offBl);
            }
            #pragma unroll
            for (int mt = 0; mt < 2; mt++)
                #pragma unroll
                for (int nt = 0; nt < NT; nt++) {
                    mma_bf16(acc[mt][nt], ah[mt][0], ah[mt][1], ah[mt][2], ah[mt][3],
                             bh[nt][0], bh[nt][1]);
                    mma_bf16(acc[mt][nt], ah[mt][0], ah[mt][1], ah[mt][2], ah[mt][3],
                             bl[nt][0], bl[nt][1]);
                    mma_bf16(acc[mt][nt], al[mt][0], al[mt][1], al[mt][2], al[mt][3],
                             bh[nt][0], bh[nt][1]);
                }
        }
        __syncthreads();
    }

    // ---- epilogue ----
    const int q = lane >> 2;        // 0..7
    const int p = lane & 3;         // 0..3
    #pragma unroll
    for (int mt = 0; mt < 2; mt++) {
        #pragma unroll
        for (int half = 0; half < 2; half++) {     // c0/c1 vs c2/c3 (row, row+8)
            const int row = rowBase + wm * 32 + mt * 16 + q + half * 8;
            #pragma unroll
            for (int nt = 0; nt < NT; nt++) {
                const int col = colBase + wn * WN + nt * 8 + p * 2;
                float v0 = acc[mt][nt][half * 2 + 0] + bias[col + 0];
                float v1 = acc[mt][nt][half * 2 + 1] + bias[col + 1];
                if (ACT) {
                    v0 = tanhf(v0); v1 = tanhf(v1);
                    __nv_bfloat16 h0, l0, h1, l1;
                    split_bf16(v0, h0, l0);
                    split_bf16(v1, h1, l1);
                    *(__nv_bfloat162*)(Ch + (size_t)row * N + col) = __halves2bfloat162(h0, h1);
                    *(__nv_bfloat162*)(Cl + (size_t)row * N + col) = __halves2bfloat162(l0, l1);
                } else {
                    *(float2*)(Cf + (size_t)row * N + col) = make_float2(v0, v1);
                }
            }
        }
    }
}

// ==================== elementwise kernels ====================
__global__ void axpy_split_kernel(__nv_bfloat16* __restrict__ outh, __nv_bfloat16* __restrict__ outl,
                                  const float* __restrict__ y, const float* __restrict__ k,
                                  const float* __restrict__ t, int step, float coef)
{
    const int i = blockIdx.x * blockDim.x + threadIdx.x;   // float4 index
    const float c = coef * (t[step + 1] - t[step]);
    float4 yv = reinterpret_cast<const float4*>(y)[i];
    float4 kv = reinterpret_cast<const float4*>(k)[i];
    float o[4];
    o[0] = fmaf(c, kv.x, yv.x); o[1] = fmaf(c, kv.y, yv.y);
    o[2] = fmaf(c, kv.z, yv.z); o[3] = fmaf(c, kv.w, yv.w);
    const int e = i * 4;
    #pragma unroll
    for (int j = 0; j < 4; j += 2) {
        __nv_bfloat16 h0, l0, h1, l1;
        split_bf16(o[j], h0, l0);
        split_bf16(o[j + 1], h1, l1);
        *(__nv_bfloat162*)(outh + e + j) = __halves2bfloat162(h0, h1);
        *(__nv_bfloat162*)(outl + e + j) = __halves2bfloat162(l0, l1);
    }
}

__global__ void rk4_final_kernel(float* __restrict__ y,
                                 __nv_bfloat16* __restrict__ yh, __nv_bfloat16* __restrict__ yl,
                                 const float* __restrict__ k1, const float* __restrict__ k2,
                                 const float* __restrict__ k3, const float* __restrict__ k4,
                                 const float* __restrict__ t, int step, float* __restrict__ out)
{
    const int i = blockIdx.x * blockDim.x + threadIdx.x;   // float4 index
    const float s = (t[step + 1] - t[step]) * (1.0f / 6.0f);
    float4 yv = reinterpret_cast<const float4*>(y)[i];
    float4 v1 = reinterpret_cast<const float4*>(k1)[i];
    float4 v2 = reinterpret_cast<const float4*>(k2)[i];
    float4 v3 = reinterpret_cast<const float4*>(k3)[i];
    float4 v4 = reinterpret_cast<const float4*>(k4)[i];
    float o[4];
    o[0] = yv.x + s * (v1.x + 2.0f * v2.x + 2.0f * v3.x + v4.x);
    o[1] = yv.y + s * (v1.y + 2.0f * v2.y + 2.0f * v3.y + v4.y);
    o[2] = yv.z + s * (v1.z + 2.0f * v2.z + 2.0f * v3.z + v4.z);
    o[3] = yv.w + s * (v1.w + 2.0f * v2.w + 2.0f * v3.w + v4.w);
    float4 ov = make_float4(o[0], o[1], o[2], o[3]);
    reinterpret_cast<float4*>(y)[i] = ov;

    const int e = i * 4;
    #pragma unroll
    for (int j = 0; j < 4; j += 2) {
        __nv_bfloat16 h0, l0, h1, l1;
        split_bf16(o[j], h0, l0);
        split_bf16(o[j + 1], h1, l1);
        *(__nv_bfloat162*)(yh + e + j) = __halves2bfloat162(h0, h1);
        *(__nv_bfloat162*)(yl + e + j) = __halves2bfloat162(l0, l1);
    }
    const int row = e / DDIM;
    const int col = e % DDIM;
    *reinterpret_cast<float4*>(&out[((size_t)row * TPTS + (step + 1)) * DDIM + col]) = ov;
}

__global__ void init_kernel(const float* __restrict__ fp, float* __restrict__ y,
                            __nv_bfloat16* __restrict__ yh, __nv_bfloat16* __restrict__ yl,
                            float* __restrict__ out, int out_size)
{
    const int i = blockIdx.x * blockDim.x + threadIdx.x;   // float4 index
    float4 v = reinterpret_cast<const float4*>(fp)[i];
    reinterpret_cast<float4*>(y)[i] = v;
    const int e = i * 4;
    float o[4] = {v.x, v.y, v.z, v.w};
    #pragma unroll
    for (int j = 0; j < 4; j += 2) {
        __nv_bfloat16 h0, l0, h1, l1;
        split_bf16(o[j], h0, l0);
        split_bf16(o[j + 1], h1, l1);
        *(__nv_bfloat162*)(yh + e + j) = __halves2bfloat162(h0, h1);
        *(__nv_bfloat162*)(yl + e + j) = __halves2bfloat162(l0, l1);
    }
    const int row = e / DDIM;
    const int col = e % DDIM;
    *reinterpret_cast<float4*>(&out[(size_t)row * TPTS * DDIM + col]) = v;
    if (i == 0) {
        const int base = MROWS * TPTS * DDIM;
        for (int z = base; z < out_size; z++) out[z] = 0.0f;
    }
}

// ==================== launch ====================
#define SMEM_128 (2 * (2 * 128 + 2 * 128) * ROWB)   // 147456
#define SMEM_64  (2 * (2 * 64 + 2 * 64) * ROWB)     // 73728

extern "C" void kernel_launch(void* const* d_in, const int* in_sizes, int n_in,
                              void* d_out, int out_size)
{
    const float* fp = (const float*)d_in[0];
    const float* t  = (const float*)d_in[1];
    const float* W1 = (const float*)d_in[2];
    const float* b1 = (const float*)d_in[3];
    const float* W2 = (const float*)d_in[4];
    const float* b2 = (const float*)d_in[5];
    const float* W3 = (const float*)d_in[6];
    const float* b3 = (const float*)d_in[7];
    float* out = (float*)d_out;

    float *y, *k1, *k2, *k3, *k4;
    __nv_bfloat16 *yh, *yl, *yth, *ytl, *h1h, *h1l, *h2h, *h2l;
    __nv_bfloat16 *w1h, *w1l, *w2h, *w2l, *w3h, *w3l;
    cudaGetSymbolAddress((void**)&y,   g_y);
    cudaGetSymbolAddress((void**)&k1,  g_k1);
    cudaGetSymbolAddress((void**)&k2,  g_k2);
    cudaGetSymbolAddress((void**)&k3,  g_k3);
    cudaGetSymbolAddress((void**)&k4,  g_k4);
    cudaGetSymbolAddress((void**)&yh,  g_yh);
    cudaGetSymbolAddress((void**)&yl,  g_yl);
    cudaGetSymbolAddress((void**)&yth, g_yth);
    cudaGetSymbolAddress((void**)&ytl, g_ytl);
    cudaGetSymbolAddress((void**)&h1h, g_h1h);
    cudaGetSymbolAddress((void**)&h1l, g_h1l);
    cudaGetSymbolAddress((void**)&h2h, g_h2h);
    cudaGetSymbolAddress((void**)&h2l, g_h2l);
    cudaGetSymbolAddress((void**)&w1h, g_w1h);
    cudaGetSymbolAddress((void**)&w1l, g_w1l);
    cudaGetSymbolAddress((void**)&w2h, g_w2h);
    cudaGetSymbolAddress((void**)&w2l, g_w2l);
    cudaGetSymbolAddress((void**)&w3h, g_w3h);
    cudaGetSymbolAddress((void**)&w3l, g_w3l);

    cudaFuncSetAttribute((const void*)gemm_mma<128, 128, 1>,
                         cudaFuncAttributeMaxDynamicSharedMemorySize, SMEM_128);
    cudaFuncSetAttribute((const void*)gemm_mma<64, 64, 0>,
                         cudaFuncAttributeMaxDynamicSharedMemorySize, SMEM_64);

    wsplit_kernel<<<(DDIM * HDIM + 255) / 256, 256>>>(W1, w1h, w1l, DDIM, HDIM);
    wsplit_kernel<<<(HDIM * HDIM + 255) / 256, 256>>>(W2, w2h, w2l, HDIM, HDIM);
    wsplit_kernel<<<(HDIM * DDIM + 255) / 256, 256>>>(W3, w3h, w3l, HDIM, DDIM);

    const int NV4 = (MROWS * DDIM) / 4;
    const dim3 ew_grid(NV4 / 256);
    init_kernel<<<ew_grid, 256>>>(fp, y, yh, yl, out, out_size);

    auto feval = [&](const __nv_bfloat16* xh, const __nv_bfloat16* xl, float* kout) {
        gemm_mma<128, 128, 1><<<dim3(HDIM / 128, MROWS / 128), 256, SMEM_128>>>(
            xh, xl, w1h, w1l, b1, h1h, h1l, nullptr, HDIM, DDIM);
        gemm_mma<128, 128, 1><<<dim3(HDIM / 128, MROWS / 128), 256, SMEM_128>>>(
            h1h, h1l, w2h, w2l, b2, h2h, h2l, nullptr, HDIM, HDIM);
        gemm_mma<64, 64, 0><<<dim3(DDIM / 64, MROWS / 64), 256, SMEM_64>>>(
            h2h, h2l, w3h, w3l, b3, nullptr, nullptr, kout, DDIM, HDIM);
    };

    for (int s = 0; s < NSTEPS; s++) {
        feval(yh, yl, k1);
        axpy_split_kernel<<<ew_grid, 256>>>(yth, ytl, y, k1, t, s, 0.5f);
        feval(yth, ytl, k2);
        axpy_split_kernel<<<ew_grid, 256>>>(yth, ytl, y, k2, t, s, 0.5f);
        feval(yth, ytl, k3);
        axpy_split_kernel<<<ew_grid, 256>>>(yth, ytl, y, k3, t, s, 1.0f);
        feval(yth, ytl, k4);
        rk4_final_kernel<<<ew_grid, 256>>>(y, yh, yl, k1, k2, k3, k4, t, s, out);
    }
}

// round 5
// speedup vs baseline: 2.9339x; 1.0067x over previous
#include <cuda_runtime.h>
#include <cuda_bf16.h>
#include <cstdint>

// Problem dims: S=4, B=512 -> M=2048; D=256; H=1024; T=50 -> 49 RK4 steps
#define MROWS 2048
#define DDIM  256
#define HDIM  1024
#define TPTS  50
#define NSTEPS (TPTS - 1)

// ==================== device scratch ====================
__device__ float g_y [MROWS * DDIM];
__device__ float g_k1[MROWS * DDIM];
__device__ float g_k2[MROWS * DDIM];
__device__ float g_k3[MROWS * DDIM];
// bf16 hi/lo splits of activations
__device__ __nv_bfloat16 g_yh [MROWS * DDIM];
__device__ __nv_bfloat16 g_yl [MROWS * DDIM];
__device__ __nv_bfloat16 g_yth[MROWS * DDIM];
__device__ __nv_bfloat16 g_ytl[MROWS * DDIM];
__device__ __nv_bfloat16 g_h1h[MROWS * HDIM];
__device__ __nv_bfloat16 g_h1l[MROWS * HDIM];
__device__ __nv_bfloat16 g_h2h[MROWS * HDIM];
__device__ __nv_bfloat16 g_h2l[MROWS * HDIM];
// transposed + split weights: Wt[N][K]
__device__ __nv_bfloat16 g_w1h[HDIM * DDIM];
__device__ __nv_bfloat16 g_w1l[HDIM * DDIM];
__device__ __nv_bfloat16 g_w2h[HDIM * HDIM];
__device__ __nv_bfloat16 g_w2l[HDIM * HDIM];
__device__ __nv_bfloat16 g_w3h[DDIM * HDIM];
__device__ __nv_bfloat16 g_w3l[DDIM * HDIM];

__device__ __forceinline__ void split_bf16(float x, __nv_bfloat16& h, __nv_bfloat16& l) {
    h = __float2bfloat16(x);
    l = __float2bfloat16(x - __bfloat162float(h));
}

// fast tanh: 1 - 2/(e^{2x}+1), via MUFU ex2 + rcp (abs err ~1e-7)
__device__ __forceinline__ float tanh_fast(float x) {
    float e;
    asm("ex2.approx.f32 %0, %1;" : "=f"(e) : "f"(x * 2.8853900817779268f));  // 2*log2(e)
    float r;
    asm("rcp.approx.f32 %0, %1;" : "=f"(r) : "f"(e + 1.0f));
    return fmaf(-2.0f, r, 1.0f);
}

__device__ __forceinline__ uint32_t smem_u32(const void* p) {
    uint32_t a;
    asm("{ .reg .u64 t; cvta.to.shared.u64 t, %1; cvt.u32.u64 %0, t; }" : "=r"(a) : "l"(p));
    return a;
}
__device__ __forceinline__ void cp_async16(uint32_t dst, const void* src) {
    asm volatile("cp.async.cg.shared.global [%0], [%1], 16;" :: "r"(dst), "l"(src) : "memory");
}
__device__ __forceinline__ void cp_commit() {
    asm volatile("cp.async.commit_group;" ::: "memory");
}
template<int N>
__device__ __forceinline__ void cp_wait() {
    asm volatile("cp.async.wait_group %0;" :: "n"(N) : "memory");
}
__device__ __forceinline__ void ldsm_x4(uint32_t& r0, uint32_t& r1, uint32_t& r2, uint32_t& r3,
                                        uint32_t addr) {
    asm volatile("ldmatrix.sync.aligned.m8n8.x4.shared.b16 {%0,%1,%2,%3}, [%4];"
                 : "=r"(r0), "=r"(r1), "=r"(r2), "=r"(r3) : "r"(addr));
}
__device__ __forceinline__ void mma_bf16(float* c, uint32_t a0, uint32_t a1, uint32_t a2,
                                         uint32_t a3, uint32_t b0, uint32_t b1) {
    asm volatile("mma.sync.aligned.m16n8k16.row.col.f32.bf16.bf16.f32 "
                 "{%0,%1,%2,%3}, {%4,%5,%6,%7}, {%8,%9}, {%0,%1,%2,%3};"
                 : "+f"(c[0]), "+f"(c[1]), "+f"(c[2]), "+f"(c[3])
                 : "r"(a0), "r"(a1), "r"(a2), "r"(a3), "r"(b0), "r"(b1));
}

// ==================== weight transpose + split ====================
__global__ void wsplit_kernel(const float* __restrict__ W, __nv_bfloat16* __restrict__ Th,
                              __nv_bfloat16* __restrict__ Tl, int K, int N) {
    int i = blockIdx.x * blockDim.x + threadIdx.x;
    if (i >= K * N) return;
    int k = i / N, n = i % N;
    __nv_bfloat16 h, l;
    split_bf16(W[i], h, l);
    Th[(size_t)n * K + k] = h;
    Tl[(size_t)n * K + k] = l;
}

// ==================== mma.sync bf16 split-3 GEMM (layers 1 & 2, tanh epilogue) ====================
#define ROWB 144

template<int BM, int BN>
__global__ __launch_bounds__(256)
void gemm_mma(const __nv_bfloat16* __restrict__ Ah, const __nv_bfloat16* __restrict__ Al,
              const __nv_bfloat16* __restrict__ Bh, const __nv_bfloat16* __restrict__ Bl,
              const float* __restrict__ bias,
              __nv_bfloat16* __restrict__ Ch, __nv_bfloat16* __restrict__ Cl,
              int N, int K)
{
    constexpr int WR = BM / 32;
    constexpr int WC = 8 / WR;
    constexpr int WN = BN / WC;
    constexpr int NT = WN / 8;
    constexpr int BUF = (2 * BM + 2 * BN) * ROWB;
    static_assert(WR * WC == 8, "warp layout");

    extern __shared__ char smem[];
    const uint32_t sbase = smem_u32(smem);

    const int tid = threadIdx.x, wid = tid >> 5, lane = tid & 31;
    const int wm = wid % WR, wn = wid / WR;
    const int rowBase = blockIdx.y * BM;
    const int colBase = blockIdx.x * BN;

    const uint32_t offAh = 0;
    const uint32_t offAl = (uint32_t)BM * ROWB;
    const uint32_t offBh = (uint32_t)2 * BM * ROWB;
    const uint32_t offBl = (uint32_t)(2 * BM + BN) * ROWB;

    const int nchunks = K >> 6;

    auto load_chunk = [&](int c, int b) {
        const uint32_t stage = sbase + (uint32_t)b * BUF;
        const int kbase = c << 6;
        #pragma unroll
        for (int u = 0; u < BM * 8 / 256; u++) {
            int idx = tid + u * 256;
            int r = idx >> 3, q = idx & 7;
            size_t g = (size_t)(rowBase + r) * K + kbase + q * 8;
            uint32_t d = (uint32_t)(r * ROWB + q * 16);
            cp_async16(stage + offAh + d, Ah + g);
            cp_async16(stage + offAl + d, Al + g);
        }
        #pragma unroll
        for (int u = 0; u < BN * 8 / 256; u++) {
            int idx = tid + u * 256;
            int r = idx >> 3, q = idx & 7;
            size_t g = (size_t)(colBase + r) * K + kbase + q * 8;
            uint32_t d = (uint32_t)(r * ROWB + q * 16);
            cp_async16(stage + offBh + d, Bh + g);
            cp_async16(stage + offBl + d, Bl + g);
        }
        cp_commit();
    };

    float acc[2][NT][4];
    #pragma unroll
    for (int mt = 0; mt < 2; mt++)
        #pragma unroll
        for (int nt = 0; nt < NT; nt++)
            #pragma unroll
            for (int j = 0; j < 4; j++)
                acc[mt][nt][j] = 0.0f;

    const int aRow = wm * 32 + (lane & 15);
    const int aByte = (lane & 16);
    const int bRow = wn * WN + ((lane & 16) >> 1) + (lane & 7);
    const int bByte = ((lane & 8) << 1);

    load_chunk(0, 0);

    for (int c = 0; c < nchunks; c++) {
        const int b = c & 1;
        if (c + 1 < nchunks) {
            load_chunk(c + 1, b ^ 1);
            cp_wait<1>();
        } else {
            cp_wait<0>();
        }
        __syncthreads();

        const uint32_t stage = sbase + (uint32_t)b * BUF;
        #pragma unroll
        for (int ks = 0; ks < 4; ks++) {
            uint32_t ah[2][4], al[2][4];
            #pragma unroll
            for (int mt = 0; mt < 2; mt++) {
                uint32_t ad = stage + (uint32_t)((aRow + mt * 16) * ROWB + ks * 32 + aByte);
                ldsm_x4(ah[mt][0], ah[mt][1], ah[mt][2], ah[mt][3], ad + offAh);
                ldsm_x4(al[mt][0], al[mt][1], al[mt][2], al[mt][3], ad + offAl);
            }
            uint32_t bh[NT][2], bl[NT][2];
            #pragma unroll
            for (int nt2 = 0; nt2 < NT / 2; nt2++) {
                uint32_t bd = stage + (uint32_t)((bRow + nt2 * 16) * ROWB + ks * 32 + bByte);
                ldsm_x4(bh[nt2 * 2][0], bh[nt2 * 2][1], bh[nt2 * 2 + 1][0], bh[nt2 * 2 + 1][1],
                        bd + offBh);
                ldsm_x4(bl[nt2 * 2][0], bl[nt2 * 2][1], bl[nt2 * 2 + 1][0], bl[nt2 * 2 + 1][1],
                        bd + offBl);
            }
            #pragma unroll
            for (int mt = 0; mt < 2; mt++)
                #pragma unroll
                for (int nt = 0; nt < NT; nt++) {
                    mma_bf16(acc[mt][nt], ah[mt][0], ah[mt][1], ah[mt][2], ah[mt][3],
                             bh[nt][0], bh[nt][1]);
                    mma_bf16(acc[mt][nt], ah[mt][0], ah[mt][1], ah[mt][2], ah[mt][3],
                             bl[nt][0], bl[nt][1]);
                    mma_bf16(acc[mt][nt], al[mt][0], al[mt][1], al[mt][2], al[mt][3],
                             bh[nt][0], bh[nt][1]);
                }
        }
        __syncthreads();
    }

    // epilogue: bias + tanh + split
    const int q = lane >> 2;
    const int p = lane & 3;
    #pragma unroll
    for (int mt = 0; mt < 2; mt++) {
        #pragma unroll
        for (int half = 0; half < 2; half++) {
            const int row = rowBase + wm * 32 + mt * 16 + q + half * 8;
            #pragma unroll
            for (int nt = 0; nt < NT; nt++) {
                const int col = colBase + wn * WN + nt * 8 + p * 2;
                float v0 = tanh_fast(acc[mt][nt][half * 2 + 0] + bias[col + 0]);
                float v1 = tanh_fast(acc[mt][nt][half * 2 + 1] + bias[col + 1]);
                __nv_bfloat16 h0, l0, h1, l1;
                split_bf16(v0, h0, l0);
                split_bf16(v1, h1, l1);
                *(__nv_bfloat162*)(Ch + (size_t)row * N + col) = __halves2bfloat162(h0, h1);
                *(__nv_bfloat162*)(Cl + (size_t)row * N + col) = __halves2bfloat162(l0, l1);
            }
        }
    }
}

// ==================== layer-3 GEMM with fused RK4 epilogue ====================
// EPI=1: k = acc+b3 -> kout (fp32); ytmp = y + coef*dt*k -> (yth,ytl) splits.
// EPI=2: k4 = acc+b3; y_next = y + dt/6*(k1+2k2+2k3+k4) -> y, (yh,yl), pred_y slice.
template<int EPI>
__global__ __launch_bounds__(256)
void gemm3_fused(const __nv_bfloat16* __restrict__ Ah, const __nv_bfloat16* __restrict__ Al,
                 const __nv_bfloat16* __restrict__ Bh, const __nv_bfloat16* __restrict__ Bl,
                 const float* __restrict__ bias,
                 float* __restrict__ y,                     // state (in; EPI=2: out)
                 float* __restrict__ kout,                  // EPI=1 out
                 const float* __restrict__ k1, const float* __restrict__ k2,
                 const float* __restrict__ k3,              // EPI=2 in
                 __nv_bfloat16* __restrict__ outh, __nv_bfloat16* __restrict__ outl,
                 float* __restrict__ pred,                  // EPI=2 out
                 const float* __restrict__ t, int step, float coef,
                 int N, int K)
{
    constexpr int BM = 64, BN = 64;
    constexpr int WR = 2, WC = 4, WN = 16, NT = 2;
    constexpr int BUF = (2 * BM + 2 * BN) * ROWB;

    extern __shared__ char smem[];
    const uint32_t sbase = smem_u32(smem);

    const int tid = threadIdx.x, wid = tid >> 5, lane = tid & 31;
    const int wm = wid % WR, wn = wid / WR;
    const int rowBase = blockIdx.y * BM;
    const int colBase = blockIdx.x * BN;

    const uint32_t offAh = 0;
    const uint32_t offAl = (uint32_t)BM * ROWB;
    const uint32_t offBh = (uint32_t)2 * BM * ROWB;
    const uint32_t offBl = (uint32_t)(2 * BM + BN) * ROWB;

    const int nchunks = K >> 6;

    auto load_chunk = [&](int c, int b) {
        const uint32_t stage = sbase + (uint32_t)b * BUF;
        const int kbase = c << 6;
        #pragma unroll
        for (int u = 0; u < BM * 8 / 256; u++) {
            int idx = tid + u * 256;
            int r = idx >> 3, qq = idx & 7;
            size_t g = (size_t)(rowBase + r) * K + kbase + qq * 8;
            uint32_t d = (uint32_t)(r * ROWB + qq * 16);
            cp_async16(stage + offAh + d, Ah + g);
            cp_async16(stage + offAl + d, Al + g);
        }
        #pragma unroll
        for (int u = 0; u < BN * 8 / 256; u++) {
            int idx = tid + u * 256;
            int r = idx >> 3, qq = idx & 7;
            size_t g = (size_t)(colBase + r) * K + kbase + qq * 8;
            uint32_t d = (uint32_t)(r * ROWB + qq * 16);
            cp_async16(stage + offBh + d, Bh + g);
            cp_async16(stage + offBl + d, Bl + g);
        }
        cp_commit();
    };

    float acc[2][NT][4];
    #pragma unroll
    for (int mt = 0; mt < 2; mt++)
        #pragma unroll
        for (int nt = 0; nt < NT; nt++)
            #pragma unroll
            for (int j = 0; j < 4; j++)
                acc[mt][nt][j] = 0.0f;

    const int aRow = wm * 32 + (lane & 15);
    const int aByte = (lane & 16);
    const int bRow = wn * WN + ((lane & 16) >> 1) + (lane & 7);
    const int bByte = ((lane & 8) << 1);

    load_chunk(0, 0);

    for (int c = 0; c < nchunks; c++) {
        const int b = c & 1;
        if (c + 1 < nchunks) {
            load_chunk(c + 1, b ^ 1);
            cp_wait<1>();
        } else {
            cp_wait<0>();
        }
        __syncthreads();

        const uint32_t stage = sbase + (uint32_t)b * BUF;
        #pragma unroll
        for (int ks = 0; ks < 4; ks++) {
            uint32_t ah[2][4], al[2][4];
            #pragma unroll
            for (int mt = 0; mt < 2; mt++) {
                uint32_t ad = stage + (uint32_t)((aRow + mt * 16) * ROWB + ks * 32 + aByte);
                ldsm_x4(ah[mt][0], ah[mt][1], ah[mt][2], ah[mt][3], ad + offAh);
                ldsm_x4(al[mt][0], al[mt][1], al[mt][2], al[mt][3], ad + offAl);
            }
            uint32_t bh[NT][2], bl[NT][2];
            {
                uint32_t bd = stage + (uint32_t)(bRow * ROWB + ks * 32 + bByte);
                ldsm_x4(bh[0][0], bh[0][1], bh[1][0], bh[1][1], bd + offBh);
                ldsm_x4(bl[0][0], bl[0][1], bl[1][0], bl[1][1], bd + offBl);
            }
            #pragma unroll
            for (int mt = 0; mt < 2; mt++)
                #pragma unroll
                for (int nt = 0; nt < NT; nt++) {
                    mma_bf16(acc[mt][nt], ah[mt][0], ah[mt][1], ah[mt][2], ah[mt][3],
                             bh[nt][0], bh[nt][1]);
                    mma_bf16(acc[mt][nt], ah[mt][0], ah[mt][1], ah[mt][2], ah[mt][3],
                             bl[nt][0], bl[nt][1]);
                    mma_bf16(acc[mt][nt], al[mt][0], al[mt][1], al[mt][2], al[mt][3],
                             bh[nt][0], bh[nt][1]);
                }
        }
        __syncthreads();
    }

    // fused RK4 epilogue
    const float dtv = t[step + 1] - t[step];
    const float cax = coef * dtv;          // EPI=1
    const float s6 = dtv * (1.0f / 6.0f);  // EPI=2
    const int q = lane >> 2;
    const int p = lane & 3;
    #pragma unroll
    for (int mt = 0; mt < 2; mt++) {
        #pragma unroll
        for (int half = 0; half < 2; half++) {
            const int row = rowBase + wm * 32 + mt * 16 + q + half * 8;
            #pragma unroll
            for (int nt = 0; nt < NT; nt++) {
                const int col = colBase + wn * WN + nt * 8 + p * 2;
                const size_t gi = (size_t)row * N + col;
                float kv0 = acc[mt][nt][half * 2 + 0] + bias[col + 0];
                float kv1 = acc[mt][nt][half * 2 + 1] + bias[col + 1];
                if (EPI == 1) {
                    *(float2*)(kout + gi) = make_float2(kv0, kv1);
                    float2 yv = *(const float2*)(y + gi);
                    float o0 = fmaf(cax, kv0, yv.x);
                    float o1 = fmaf(cax, kv1, yv.y);
                    __nv_bfloat16 h0, l0, h1, l1;
                    split_bf16(o0, h0, l0);
                    split_bf16(o1, h1, l1);
                    *(__nv_bfloat162*)(outh + gi) = __halves2bfloat162(h0, h1);
                    *(__nv_bfloat162*)(outl + gi) = __halves2bfloat162(l0, l1);
                } else {
                    float2 yv = *(const float2*)(y + gi);
                    float2 a1 = *(const float2*)(k1 + gi);
                    float2 a2 = *(const float2*)(k2 + gi);
                    float2 a3 = *(const float2*)(k3 + gi);
                    float o0 = yv.x + s6 * (a1.x + 2.0f * a2.x + 2.0f * a3.x + kv0);
                    float o1 = yv.y + s6 * (a1.y + 2.0f * a2.y + 2.0f * a3.y + kv1);
                    *(float2*)(y + gi) = make_float2(o0, o1);
                    __nv_bfloat16 h0, l0, h1, l1;
                    split_bf16(o0, h0, l0);
                    split_bf16(o1, h1, l1);
                    *(__nv_bfloat162*)(outh + gi) = __halves2bfloat162(h0, h1);
                    *(__nv_bfloat162*)(outl + gi) = __halves2bfloat162(l0, l1);
                    *(float2*)(pred + ((size_t)row * TPTS + (step + 1)) * DDIM + col) =
                        make_float2(o0, o1);
                }
            }
        }
    }
}

// ==================== init ====================
__global__ void init_kernel(const float* __restrict__ fp, float* __restrict__ y,
                            __nv_bfloat16* __restrict__ yh, __nv_bfloat16* __restrict__ yl,
                            float* __restrict__ out, int out_size)
{
    const int i = blockIdx.x * blockDim.x + threadIdx.x;   // float4 index
    float4 v = reinterpret_cast<const float4*>(fp)[i];
    reinterpret_cast<float4*>(y)[i] = v;
    const int e = i * 4;
    float o[4] = {v.x, v.y, v.z, v.w};
    #pragma unroll
    for (int j = 0; j < 4; j += 2) {
        __nv_bfloat16 h0, l0, h1, l1;
        split_bf16(o[j], h0, l0);
        split_bf16(o[j + 1], h1, l1);
        *(__nv_bfloat162*)(yh + e + j) = __halves2bfloat162(h0, h1);
        *(__nv_bfloat162*)(yl + e + j) = __halves2bfloat162(l0, l1);
    }
    const int row = e / DDIM;
    const int col = e % DDIM;
    *reinterpret_cast<float4*>(&out[(size_t)row * TPTS * DDIM + col]) = v;
    if (i == 0) {
        const int base = MROWS * TPTS * DDIM;
        for (int z = base; z < out_size; z++) out[z] = 0.0f;
    }
}

// ==================== launch ====================
#define SMEM_128 (2 * (2 * 128 + 2 * 128) * ROWB)   // 147456
#define SMEM_64  (2 * (2 * 64 + 2 * 64) * ROWB)     // 73728

extern "C" void kernel_launch(void* const* d_in, const int* in_sizes, int n_in,
                              void* d_out, int out_size)
{
    const float* fp = (const float*)d_in[0];
    const float* t  = (const float*)d_in[1];
    const float* W1 = (const float*)d_in[2];
    const float* b1 = (const float*)d_in[3];
    const float* W2 = (const float*)d_in[4];
    const float* b2 = (const float*)d_in[5];
    const float* W3 = (const float*)d_in[6];
    const float* b3 = (const float*)d_in[7];
    float* out = (float*)d_out;

    float *y, *k1, *k2, *k3;
    __nv_bfloat16 *yh, *yl, *yth, *ytl, *h1h, *h1l, *h2h, *h2l;
    __nv_bfloat16 *w1h, *w1l, *w2h, *w2l, *w3h, *w3l;
    cudaGetSymbolAddress((void**)&y,   g_y);
    cudaGetSymbolAddress((void**)&k1,  g_k1);
    cudaGetSymbolAddress((void**)&k2,  g_k2);
    cudaGetSymbolAddress((void**)&k3,  g_k3);
    cudaGetSymbolAddress((void**)&yh,  g_yh);
    cudaGetSymbolAddress((void**)&yl,  g_yl);
    cudaGetSymbolAddress((void**)&yth, g_yth);
    cudaGetSymbolAddress((void**)&ytl, g_ytl);
    cudaGetSymbolAddress((void**)&h1h, g_h1h);
    cudaGetSymbolAddress((void**)&h1l, g_h1l);
    cudaGetSymbolAddress((void**)&h2h, g_h2h);
    cudaGetSymbolAddress((void**)&h2l, g_h2l);
    cudaGetSymbolAddress((void**)&w1h, g_w1h);
    cudaGetSymbolAddress((void**)&w1l, g_w1l);
    cudaGetSymbolAddress((void**)&w2h, g_w2h);
    cudaGetSymbolAddress((void**)&w2l, g_w2l);
    cudaGetSymbolAddress((void**)&w3h, g_w3h);
    cudaGetSymbolAddress((void**)&w3l, g_w3l);

    cudaFuncSetAttribute((const void*)gemm_mma<128, 128>,
                         cudaFuncAttributeMaxDynamicSharedMemorySize, SMEM_128);
    cudaFuncSetAttribute((const void*)gemm3_fused<1>,
                         cudaFuncAttributeMaxDynamicSharedMemorySize, SMEM_64);
    cudaFuncSetAttribute((const void*)gemm3_fused<2>,
                         cudaFuncAttributeMaxDynamicSharedMemorySize, SMEM_64);

    wsplit_kernel<<<(DDIM * HDIM + 255) / 256, 256>>>(W1, w1h, w1l, DDIM, HDIM);
    wsplit_kernel<<<(HDIM * HDIM + 255) / 256, 256>>>(W2, w2h, w2l, HDIM, HDIM);
    wsplit_kernel<<<(HDIM * DDIM + 255) / 256, 256>>>(W3, w3h, w3l, HDIM, DDIM);

    const int NV4 = (MROWS * DDIM) / 4;
    const dim3 ew_grid(NV4 / 256);
    init_kernel<<<ew_grid, 256>>>(fp, y, yh, yl, out, out_size);

    const dim3 g12(HDIM / 128, MROWS / 128);
    const dim3 g3(DDIM / 64, MROWS / 64);

    auto mlp12 = [&](const __nv_bfloat16* xh, const __nv_bfloat16* xl) {
        gemm_mma<128, 128><<<g12, 256, SMEM_128>>>(xh, xl, w1h, w1l, b1, h1h, h1l, HDIM, DDIM);
        gemm_mma<128, 128><<<g12, 256, SMEM_128>>>(h1h, h1l, w2h, w2l, b2, h2h, h2l, HDIM, HDIM);
    };

    for (int s = 0; s < NSTEPS; s++) {
        mlp12(yh, yl);
        gemm3_fused<1><<<g3, 256, SMEM_64>>>(h2h, h2l, w3h, w3l, b3, y, k1,
                                             nullptr, nullptr, nullptr,
                                             yth, ytl, nullptr, t, s, 0.5f, DDIM, HDIM);
        mlp12(yth, ytl);
        gemm3_fused<1><<<g3, 256, SMEM_64>>>(h2h, h2l, w3h, w3l, b3, y, k2,
                                             nullptr, nullptr, nullptr,
                                             yth, ytl, nullptr, t, s, 0.5f, DDIM, HDIM);
        mlp12(yth, ytl);
        gemm3_fused<1><<<g3, 256, SMEM_64>>>(h2h, h2l, w3h, w3l, b3, y, k3,
                                             nullptr, nullptr, nullptr,
                                             yth, ytl, nullptr, t, s, 1.0f, DDIM, HDIM);
        mlp12(yth, ytl);
        gemm3_fused<2><<<g3, 256, SMEM_64>>>(h2h, h2l, w3h, w3l, b3, y, nullptr,
                                             k1, k2, k3,
                                             yh, yl, out, t, s, 0.0f, DDIM, HDIM);
    }
}

// round 6
// speedup vs baseline: 2.9380x; 1.0014x over previous
#include <cuda_runtime.h>
#include <cuda_bf16.h>
#include <cstdint>

// Problem dims: S=4, B=512 -> M=2048; D=256; H=1024; T=50 -> 49 RK4 steps
#define MROWS 2048
#define DDIM  256
#define HDIM  1024
#define TPTS  50
#define NSTEPS (TPTS - 1)

// ==================== device scratch ====================
__device__ float g_y [MROWS * DDIM];
__device__ float g_k1[MROWS * DDIM];
__device__ float g_k2[MROWS * DDIM];
__device__ float g_k3[MROWS * DDIM];
__device__ __nv_bfloat16 g_yh [MROWS * DDIM];
__device__ __nv_bfloat16 g_yl [MROWS * DDIM];
__device__ __nv_bfloat16 g_yth[MROWS * DDIM];
__device__ __nv_bfloat16 g_ytl[MROWS * DDIM];
__device__ __nv_bfloat16 g_h1h[MROWS * HDIM];
__device__ __nv_bfloat16 g_h1l[MROWS * HDIM];
__device__ __nv_bfloat16 g_h2h[MROWS * HDIM];
__device__ __nv_bfloat16 g_h2l[MROWS * HDIM];
__device__ __nv_bfloat16 g_w1h[HDIM * DDIM];
__device__ __nv_bfloat16 g_w1l[HDIM * DDIM];
__device__ __nv_bfloat16 g_w2h[HDIM * HDIM];
__device__ __nv_bfloat16 g_w2l[HDIM * HDIM];
__device__ __nv_bfloat16 g_w3h[DDIM * HDIM];
__device__ __nv_bfloat16 g_w3l[DDIM * HDIM];

__device__ __forceinline__ void split_bf16(float x, __nv_bfloat16& h, __nv_bfloat16& l) {
    h = __float2bfloat16(x);
    l = __float2bfloat16(x - __bfloat162float(h));
}

// fast tanh: 1 - 2/(e^{2x}+1), via MUFU ex2 + rcp (abs err ~1e-7)
__device__ __forceinline__ float tanh_fast(float x) {
    float e;
    asm("ex2.approx.f32 %0, %1;" : "=f"(e) : "f"(x * 2.8853900817779268f));
    float r;
    asm("rcp.approx.f32 %0, %1;" : "=f"(r) : "f"(e + 1.0f));
    return fmaf(-2.0f, r, 1.0f);
}

__device__ __forceinline__ uint32_t smem_u32(const void* p) {
    uint32_t a;
    asm("{ .reg .u64 t; cvta.to.shared.u64 t, %1; cvt.u32.u64 %0, t; }" : "=r"(a) : "l"(p));
    return a;
}
__device__ __forceinline__ void cp_async16(uint32_t dst, const void* src) {
    asm volatile("cp.async.cg.shared.global [%0], [%1], 16;" :: "r"(dst), "l"(src) : "memory");
}
__device__ __forceinline__ void cp_commit() {
    asm volatile("cp.async.commit_group;" ::: "memory");
}
template<int N>
__device__ __forceinline__ void cp_wait() {
    asm volatile("cp.async.wait_group %0;" :: "n"(N) : "memory");
}
__device__ __forceinline__ void ldsm_x4(uint32_t& r0, uint32_t& r1, uint32_t& r2, uint32_t& r3,
                                        uint32_t addr) {
    asm volatile("ldmatrix.sync.aligned.m8n8.x4.shared.b16 {%0,%1,%2,%3}, [%4];"
                 : "=r"(r0), "=r"(r1), "=r"(r2), "=r"(r3) : "r"(addr));
}
__device__ __forceinline__ void mma_bf16(float* c, uint32_t a0, uint32_t a1, uint32_t a2,
                                         uint32_t a3, uint32_t b0, uint32_t b1) {
    asm volatile("mma.sync.aligned.m16n8k16.row.col.f32.bf16.bf16.f32 "
                 "{%0,%1,%2,%3}, {%4,%5,%6,%7}, {%8,%9}, {%0,%1,%2,%3};"
                 : "+f"(c[0]), "+f"(c[1]), "+f"(c[2]), "+f"(c[3])
                 : "r"(a0), "r"(a1), "r"(a2), "r"(a3), "r"(b0), "r"(b1));
}

// ==================== weight transpose + split ====================
__global__ void wsplit_kernel(const float* __restrict__ W, __nv_bfloat16* __restrict__ Th,
                              __nv_bfloat16* __restrict__ Tl, int K, int N) {
    int i = blockIdx.x * blockDim.x + threadIdx.x;
    if (i >= K * N) return;
    int k = i / N, n = i % N;
    __nv_bfloat16 h, l;
    split_bf16(W[i], h, l);
    Th[(size_t)n * K + k] = h;
    Tl[(size_t)n * K + k] = l;
}

// ==================== mma.sync bf16 split-3 GEMM (layers 1 & 2) ====================
#define ROWB 144

template<int BM, int BN>
__global__ __launch_bounds__(256)
void gemm_mma(const __nv_bfloat16* __restrict__ Ah, const __nv_bfloat16* __restrict__ Al,
              const __nv_bfloat16* __restrict__ Bh, const __nv_bfloat16* __restrict__ Bl,
              const float* __restrict__ bias,
              __nv_bfloat16* __restrict__ Ch, __nv_bfloat16* __restrict__ Cl,
              int N, int K)
{
    constexpr int WR = BM / 32;
    constexpr int WC = 8 / WR;
    constexpr int WN = BN / WC;
    constexpr int NT = WN / 8;
    constexpr int BUF = (2 * BM + 2 * BN) * ROWB;
    static_assert(WR * WC == 8, "warp layout");

    extern __shared__ char smem[];
    const uint32_t sbase = smem_u32(smem);

    const int tid = threadIdx.x, wid = tid >> 5, lane = tid & 31;
    const int wm = wid % WR, wn = wid / WR;
    const int rowBase = blockIdx.y * BM;
    const int colBase = blockIdx.x * BN;

    const uint32_t offAh = 0;
    const uint32_t offAl = (uint32_t)BM * ROWB;
    const uint32_t offBh = (uint32_t)2 * BM * ROWB;
    const uint32_t offBl = (uint32_t)(2 * BM + BN) * ROWB;

    const int nchunks = K >> 6;

    auto load_chunk = [&](int c, int b) {
        const uint32_t stage = sbase + (uint32_t)b * BUF;
        const int kbase = c << 6;
        #pragma unroll
        for (int u = 0; u < BM * 8 / 256; u++) {
            int idx = tid + u * 256;
            int r = idx >> 3, q = idx & 7;
            size_t g = (size_t)(rowBase + r) * K + kbase + q * 8;
            uint32_t d = (uint32_t)(r * ROWB + q * 16);
            cp_async16(stage + offAh + d, Ah + g);
            cp_async16(stage + offAl + d, Al + g);
        }
        #pragma unroll
        for (int u = 0; u < BN * 8 / 256; u++) {
            int idx = tid + u * 256;
            int r = idx >> 3, q = idx & 7;
            size_t g = (size_t)(colBase + r) * K + kbase + q * 8;
            uint32_t d = (uint32_t)(r * ROWB + q * 16);
            cp_async16(stage + offBh + d, Bh + g);
            cp_async16(stage + offBl + d, Bl + g);
        }
        cp_commit();
    };

    float acc[2][NT][4];
    #pragma unroll
    for (int mt = 0; mt < 2; mt++)
        #pragma unroll
        for (int nt = 0; nt < NT; nt++)
            #pragma unroll
            for (int j = 0; j < 4; j++)
                acc[mt][nt][j] = 0.0f;

    const int aRow = wm * 32 + (lane & 15);
    const int aByte = (lane & 16);
    const int bRow = wn * WN + ((lane & 16) >> 1) + (lane & 7);
    const int bByte = ((lane & 8) << 1);

    load_chunk(0, 0);

    for (int c = 0; c < nchunks; c++) {
        const int b = c & 1;
        if (c + 1 < nchunks) {
            load_chunk(c + 1, b ^ 1);
            cp_wait<1>();
        } else {
            cp_wait<0>();
        }
        __syncthreads();

        const uint32_t stage = sbase + (uint32_t)b * BUF;
        #pragma unroll
        for (int ks = 0; ks < 4; ks++) {
            uint32_t ah[2][4], al[2][4];
            #pragma unroll
            for (int mt = 0; mt < 2; mt++) {
                uint32_t ad = stage + (uint32_t)((aRow + mt * 16) * ROWB + ks * 32 + aByte);
                ldsm_x4(ah[mt][0], ah[mt][1], ah[mt][2], ah[mt][3], ad + offAh);
                ldsm_x4(al[mt][0], al[mt][1], al[mt][2], al[mt][3], ad + offAl);
            }
            uint32_t bh[NT][2], bl[NT][2];
            #pragma unroll
            for (int nt2 = 0; nt2 < NT / 2; nt2++) {
                uint32_t bd = stage + (uint32_t)((bRow + nt2 * 16) * ROWB + ks * 32 + bByte);
                ldsm_x4(bh[nt2 * 2][0], bh[nt2 * 2][1], bh[nt2 * 2 + 1][0], bh[nt2 * 2 + 1][1],
                        bd + offBh);
                ldsm_x4(bl[nt2 * 2][0], bl[nt2 * 2][1], bl[nt2 * 2 + 1][0], bl[nt2 * 2 + 1][1],
                        bd + offBl);
            }
            // product-major ordering: all accs are touched once per pass ->
            // 2*NT independent HMMAs between same-acc reuses (no RAW chains)
            #pragma unroll
            for (int mt = 0; mt < 2; mt++)
                #pragma unroll
                for (int nt = 0; nt < NT; nt++)
                    mma_bf16(acc[mt][nt], ah[mt][0], ah[mt][1], ah[mt][2], ah[mt][3],
                             bh[nt][0], bh[nt][1]);
            #pragma unroll
            for (int mt = 0; mt < 2; mt++)
                #pragma unroll
                for (int nt = 0; nt < NT; nt++)
                    mma_bf16(acc[mt][nt], ah[mt][0], ah[mt][1], ah[mt][2], ah[mt][3],
                             bl[nt][0], bl[nt][1]);
            #pragma unroll
            for (int mt = 0; mt < 2; mt++)
                #pragma unroll
                for (int nt = 0; nt < NT; nt++)
                    mma_bf16(acc[mt][nt], al[mt][0], al[mt][1], al[mt][2], al[mt][3],
                             bh[nt][0], bh[nt][1]);
        }
        __syncthreads();
    }

    const int q = lane >> 2;
    const int p = lane & 3;
    #pragma unroll
    for (int mt = 0; mt < 2; mt++) {
        #pragma unroll
        for (int half = 0; half < 2; half++) {
            const int row = rowBase + wm * 32 + mt * 16 + q + half * 8;
            #pragma unroll
            for (int nt = 0; nt < NT; nt++) {
                const int col = colBase + wn * WN + nt * 8 + p * 2;
                float v0 = tanh_fast(acc[mt][nt][half * 2 + 0] + bias[col + 0]);
                float v1 = tanh_fast(acc[mt][nt][half * 2 + 1] + bias[col + 1]);
                __nv_bfloat16 h0, l0, h1, l1;
                split_bf16(v0, h0, l0);
                split_bf16(v1, h1, l1);
                *(__nv_bfloat162*)(Ch + (size_t)row * N + col) = __halves2bfloat162(h0, h1);
                *(__nv_bfloat162*)(Cl + (size_t)row * N + col) = __halves2bfloat162(l0, l1);
            }
        }
    }
}

// ==================== layer-3 GEMM with fused RK4 epilogue ====================
template<int EPI>
__global__ __launch_bounds__(256)
void gemm3_fused(const __nv_bfloat16* __restrict__ Ah, const __nv_bfloat16* __restrict__ Al,
                 const __nv_bfloat16* __restrict__ Bh, const __nv_bfloat16* __restrict__ Bl,
                 const float* __restrict__ bias,
                 float* __restrict__ y,
                 float* __restrict__ kout,
                 const float* __restrict__ k1, const float* __restrict__ k2,
                 const float* __restrict__ k3,
                 __nv_bfloat16* __restrict__ outh, __nv_bfloat16* __restrict__ outl,
                 float* __restrict__ pred,
                 const float* __restrict__ t, int step, float coef,
                 int N, int K)
{
    constexpr int BM = 64, BN = 64;
    constexpr int WR = 2, WC = 4, WN = 16, NT = 2;
    constexpr int BUF = (2 * BM + 2 * BN) * ROWB;

    extern __shared__ char smem[];
    const uint32_t sbase = smem_u32(smem);

    const int tid = threadIdx.x, wid = tid >> 5, lane = tid & 31;
    const int wm = wid % WR, wn = wid / WR;
    const int rowBase = blockIdx.y * BM;
    const int colBase = blockIdx.x * BN;

    const uint32_t offAh = 0;
    const uint32_t offAl = (uint32_t)BM * ROWB;
    const uint32_t offBh = (uint32_t)2 * BM * ROWB;
    const uint32_t offBl = (uint32_t)(2 * BM + BN) * ROWB;

    const int nchunks = K >> 6;

    auto load_chunk = [&](int c, int b) {
        const uint32_t stage = sbase + (uint32_t)b * BUF;
        const int kbase = c << 6;
        #pragma unroll
        for (int u = 0; u < BM * 8 / 256; u++) {
            int idx = tid + u * 256;
            int r = idx >> 3, qq = idx & 7;
            size_t g = (size_t)(rowBase + r) * K + kbase + qq * 8;
            uint32_t d = (uint32_t)(r * ROWB + qq * 16);
            cp_async16(stage + offAh + d, Ah + g);
            cp_async16(stage + offAl + d, Al + g);
        }
        #pragma unroll
        for (int u = 0; u < BN * 8 / 256; u++) {
            int idx = tid + u * 256;
            int r = idx >> 3, qq = idx & 7;
            size_t g = (size_t)(colBase + r) * K + kbase + qq * 8;
            uint32_t d = (uint32_t)(r * ROWB + qq * 16);
            cp_async16(stage + offBh + d, Bh + g);
            cp_async16(stage + offBl + d, Bl + g);
        }
        cp_commit();
    };

    float acc[2][NT][4];
    #pragma unroll
    for (int mt = 0; mt < 2; mt++)
        #pragma unroll
        for (int nt = 0; nt < NT; nt++)
            #pragma unroll
            for (int j = 0; j < 4; j++)
                acc[mt][nt][j] = 0.0f;

    const int aRow = wm * 32 + (lane & 15);
    const int aByte = (lane & 16);
    const int bRow = wn * WN + ((lane & 16) >> 1) + (lane & 7);
    const int bByte = ((lane & 8) << 1);

    load_chunk(0, 0);

    for (int c = 0; c < nchunks; c++) {
        const int b = c & 1;
        if (c + 1 < nchunks) {
            load_chunk(c + 1, b ^ 1);
            cp_wait<1>();
        } else {
            cp_wait<0>();
        }
        __syncthreads();

        const uint32_t stage = sbase + (uint32_t)b * BUF;
        #pragma unroll
        for (int ks = 0; ks < 4; ks++) {
            uint32_t ah[2][4], al[2][4];
            #pragma unroll
            for (int mt = 0; mt < 2; mt++) {
                uint32_t ad = stage + (uint32_t)((aRow + mt * 16) * ROWB + ks * 32 + aByte);
                ldsm_x4(ah[mt][0], ah[mt][1], ah[mt][2], ah[mt][3], ad + offAh);
                ldsm_x4(al[mt][0], al[mt][1], al[mt][2], al[mt][3], ad + offAl);
            }
            uint32_t bh[NT][2], bl[NT][2];
            {
                uint32_t bd = stage + (uint32_t)(bRow * ROWB + ks * 32 + bByte);
                ldsm_x4(bh[0][0], bh[0][1], bh[1][0], bh[1][1], bd + offBh);
                ldsm_x4(bl[0][0], bl[0][1], bl[1][0], bl[1][1], bd + offBl);
            }
            #pragma unroll
            for (int mt = 0; mt < 2; mt++)
                #pragma unroll
                for (int nt = 0; nt < NT; nt++)
                    mma_bf16(acc[mt][nt], ah[mt][0], ah[mt][1], ah[mt][2], ah[mt][3],
                             bh[nt][0], bh[nt][1]);
            #pragma unroll
            for (int mt = 0; mt < 2; mt++)
                #pragma unroll
                for (int nt = 0; nt < NT; nt++)
                    mma_bf16(acc[mt][nt], ah[mt][0], ah[mt][1], ah[mt][2], ah[mt][3],
                             bl[nt][0], bl[nt][1]);
            #pragma unroll
            for (int mt = 0; mt < 2; mt++)
                #pragma unroll
                for (int nt = 0; nt < NT; nt++)
                    mma_bf16(acc[mt][nt], al[mt][0], al[mt][1], al[mt][2], al[mt][3],
                             bh[nt][0], bh[nt][1]);
        }
        __syncthreads();
    }

    const float dtv = t[step + 1] - t[step];
    const float cax = coef * dtv;
    const float s6 = dtv * (1.0f / 6.0f);
    const int q = lane >> 2;
    const int p = lane & 3;
    #pragma unroll
    for (int mt = 0; mt < 2; mt++) {
        #pragma unroll
        for (int half = 0; half < 2; half++) {
            const int row = rowBase + wm * 32 + mt * 16 + q + half * 8;
            #pragma unroll
            for (int nt = 0; nt < NT; nt++) {
                const int col = colBase + wn * WN + nt * 8 + p * 2;
                const size_t gi = (size_t)row * N + col;
                float kv0 = acc[mt][nt][half * 2 + 0] + bias[col + 0];
                float kv1 = acc[mt][nt][half * 2 + 1] + bias[col + 1];
                if (EPI == 1) {
                    *(float2*)(kout + gi) = make_float2(kv0, kv1);
                    float2 yv = *(const float2*)(y + gi);
                    float o0 = fmaf(cax, kv0, yv.x);
                    float o1 = fmaf(cax, kv1, yv.y);
                    __nv_bfloat16 h0, l0, h1, l1;
                    split_bf16(o0, h0, l0);
                    split_bf16(o1, h1, l1);
                    *(__nv_bfloat162*)(outh + gi) = __halves2bfloat162(h0, h1);
                    *(__nv_bfloat162*)(outl + gi) = __halves2bfloat162(l0, l1);
                } else {
                    float2 yv = *(const float2*)(y + gi);
                    float2 a1 = *(const float2*)(k1 + gi);
                    float2 a2 = *(const float2*)(k2 + gi);
                    float2 a3 = *(const float2*)(k3 + gi);
                    float o0 = yv.x + s6 * (a1.x + 2.0f * a2.x + 2.0f * a3.x + kv0);
                    float o1 = yv.y + s6 * (a1.y + 2.0f * a2.y + 2.0f * a3.y + kv1);
                    *(float2*)(y + gi) = make_float2(o0, o1);
                    __nv_bfloat16 h0, l0, h1, l1;
                    split_bf16(o0, h0, l0);
                    split_bf16(o1, h1, l1);
                    *(__nv_bfloat162*)(outh + gi) = __halves2bfloat162(h0, h1);
                    *(__nv_bfloat162*)(outl + gi) = __halves2bfloat162(l0, l1);
                    *(float2*)(pred + ((size_t)row * TPTS + (step + 1)) * DDIM + col) =
                        make_float2(o0, o1);
                }
            }
        }
    }
}

// ==================== init ====================
__global__ void init_kernel(const float* __restrict__ fp, float* __restrict__ y,
                            __nv_bfloat16* __restrict__ yh, __nv_bfloat16* __restrict__ yl,
                            float* __restrict__ out, int out_size)
{
    const int i = blockIdx.x * blockDim.x + threadIdx.x;
    float4 v = reinterpret_cast<const float4*>(fp)[i];
    reinterpret_cast<float4*>(y)[i] = v;
    const int e = i * 4;
    float o[4] = {v.x, v.y, v.z, v.w};
    #pragma unroll
    for (int j = 0; j < 4; j += 2) {
        __nv_bfloat16 h0, l0, h1, l1;
        split_bf16(o[j], h0, l0);
        split_bf16(o[j + 1], h1, l1);
        *(__nv_bfloat162*)(yh + e + j) = __halves2bfloat162(h0, h1);
        *(__nv_bfloat162*)(yl + e + j) = __halves2bfloat162(l0, l1);
    }
    const int row = e / DDIM;
    const int col = e % DDIM;
    *reinterpret_cast<float4*>(&out[(size_t)row * TPTS * DDIM + col]) = v;
    if (i == 0) {
        const int base = MROWS * TPTS * DDIM;
        for (int z = base; z < out_size; z++) out[z] = 0.0f;
    }
}

// ==================== launch ====================
#define SMEM_128 (2 * (2 * 128 + 2 * 128) * ROWB)
#define SMEM_64  (2 * (2 * 64 + 2 * 64) * ROWB)

extern "C" void kernel_launch(void* const* d_in, const int* in_sizes, int n_in,
                              void* d_out, int out_size)
{
    const float* fp = (const float*)d_in[0];
    const float* t  = (const float*)d_in[1];
    const float* W1 = (const float*)d_in[2];
    const float* b1 = (const float*)d_in[3];
    const float* W2 = (const float*)d_in[4];
    const float* b2 = (const float*)d_in[5];
    const float* W3 = (const float*)d_in[6];
    const float* b3 = (const float*)d_in[7];
    float* out = (float*)d_out;

    float *y, *k1, *k2, *k3;
    __nv_bfloat16 *yh, *yl, *yth, *ytl, *h1h, *h1l, *h2h, *h2l;
    __nv_bfloat16 *w1h, *w1l, *w2h, *w2l, *w3h, *w3l;
    cudaGetSymbolAddress((void**)&y,   g_y);
    cudaGetSymbolAddress((void**)&k1,  g_k1);
    cudaGetSymbolAddress((void**)&k2,  g_k2);
    cudaGetSymbolAddress((void**)&k3,  g_k3);
    cudaGetSymbolAddress((void**)&yh,  g_yh);
    cudaGetSymbolAddress((void**)&yl,  g_yl);
    cudaGetSymbolAddress((void**)&yth, g_yth);
    cudaGetSymbolAddress((void**)&ytl, g_ytl);
    cudaGetSymbolAddress((void**)&h1h, g_h1h);
    cudaGetSymbolAddress((void**)&h1l, g_h1l);
    cudaGetSymbolAddress((void**)&h2h, g_h2h);
    cudaGetSymbolAddress((void**)&h2l, g_h2l);
    cudaGetSymbolAddress((void**)&w1h, g_w1h);
    cudaGetSymbolAddress((void**)&w1l, g_w1l);
    cudaGetSymbolAddress((void**)&w2h, g_w2h);
    cudaGetSymbolAddress((void**)&w2l, g_w2l);
    cudaGetSymbolAddress((void**)&w3h, g_w3h);
    cudaGetSymbolAddress((void**)&w3l, g_w3l);

    cudaFuncSetAttribute((const void*)gemm_mma<128, 128>,
                         cudaFuncAttributeMaxDynamicSharedMemorySize, SMEM_128);
    cudaFuncSetAttribute((const void*)gemm3_fused<1>,
                         cudaFuncAttributeMaxDynamicSharedMemorySize, SMEM_64);
    cudaFuncSetAttribute((const void*)gemm3_fused<2>,
                         cudaFuncAttributeMaxDynamicSharedMemorySize, SMEM_64);

    wsplit_kernel<<<(DDIM * HDIM + 255) / 256, 256>>>(W1, w1h, w1l, DDIM, HDIM);
    wsplit_kernel<<<(HDIM * HDIM + 255) / 256, 256>>>(W2, w2h, w2l, HDIM, HDIM);
    wsplit_kernel<<<(HDIM * DDIM + 255) / 256, 256>>>(W3, w3h, w3l, HDIM, DDIM);

    const int NV4 = (MROWS * DDIM) / 4;
    const dim3 ew_grid(NV4 / 256);
    init_kernel<<<ew_grid, 256>>>(fp, y, yh, yl, out, out_size);

    const dim3 g12(HDIM / 128, MROWS / 128);
    const dim3 g3(DDIM / 64, MROWS / 64);

    auto mlp12 = [&](const __nv_bfloat16* xh, const __nv_bfloat16* xl) {
        gemm_mma<128, 128><<<g12, 256, SMEM_128>>>(xh, xl, w1h, w1l, b1, h1h, h1l, HDIM, DDIM);
        gemm_mma<128, 128><<<g12, 256, SMEM_128>>>(h1h, h1l, w2h, w2l, b2, h2h, h2l, HDIM, HDIM);
    };

    for (int s = 0; s < NSTEPS; s++) {
        mlp12(yh, yl);
        gemm3_fused<1><<<g3, 256, SMEM_64>>>(h2h, h2l, w3h, w3l, b3, y, k1,
                                             nullptr, nullptr, nullptr,
                                             yth, ytl, nullptr, t, s, 0.5f, DDIM, HDIM);
        mlp12(yth, ytl);
        gemm3_fused<1><<<g3, 256, SMEM_64>>>(h2h, h2l, w3h, w3l, b3, y, k2,
                                             nullptr, nullptr, nullptr,
                                             yth, ytl, nullptr, t, s, 0.5f, DDIM, HDIM);
        mlp12(yth, ytl);
        gemm3_fused<1><<<g3, 256, SMEM_64>>>(h2h, h2l, w3h, w3l, b3, y, k3,
                                             nullptr, nullptr, nullptr,
                                             yth, ytl, nullptr, t, s, 1.0f, DDIM, HDIM);
        mlp12(yth, ytl);
        gemm3_fused<2><<<g3, 256, SMEM_64>>>(h2h, h2l, w3h, w3l, b3, y, nullptr,
                                             k1, k2, k3,
                                             yh, yl, out, t, s, 0.0f, DDIM, HDIM);
    }
}

// round 7
// speedup vs baseline: 4.1369x; 1.4081x over previous
#include <cuda_runtime.h>
#include <cuda_fp16.h>
#include <cstdint>

// Problem dims: S=4, B=512 -> M=2048; D=256; H=1024; T=50 -> 49 RK4 steps
#define MROWS 2048
#define DDIM  256
#define HDIM  1024
#define TPTS  50
#define NSTEPS (TPTS - 1)

// ==================== device scratch ====================
__device__ float g_y [MROWS * DDIM];
__device__ float g_k1[MROWS * DDIM];
__device__ float g_k2[MROWS * DDIM];
__device__ float g_k3[MROWS * DDIM];
// fp16 activations (single precision-rounded copies)
__device__ __half g_yq [MROWS * DDIM];
__device__ __half g_ytq[MROWS * DDIM];
__device__ __half g_h1q[MROWS * HDIM];
__device__ __half g_h2q[MROWS * HDIM];
// transposed + split weights: Wt[N][K] fp16 hi/lo
__device__ __half g_w1h[HDIM * DDIM];
__device__ __half g_w1l[HDIM * DDIM];
__device__ __half g_w2h[HDIM * HDIM];
__device__ __half g_w2l[HDIM * HDIM];
__device__ __half g_w3h[DDIM * HDIM];
__device__ __half g_w3l[DDIM * HDIM];

__device__ __forceinline__ void split_fp16(float x, __half& h, __half& l) {
    h = __float2half(x);
    l = __float2half(x - __half2float(h));
}

// fast tanh: 1 - 2/(e^{2x}+1), via MUFU ex2 + rcp (abs err ~1e-7)
__device__ __forceinline__ float tanh_fast(float x) {
    float e;
    asm("ex2.approx.f32 %0, %1;" : "=f"(e) : "f"(x * 2.8853900817779268f));
    float r;
    asm("rcp.approx.f32 %0, %1;" : "=f"(r) : "f"(e + 1.0f));
    return fmaf(-2.0f, r, 1.0f);
}

__device__ __forceinline__ uint32_t smem_u32(const void* p) {
    uint32_t a;
    asm("{ .reg .u64 t; cvta.to.shared.u64 t, %1; cvt.u32.u64 %0, t; }" : "=r"(a) : "l"(p));
    return a;
}
__device__ __forceinline__ void cp_async16(uint32_t dst, const void* src) {
    asm volatile("cp.async.cg.shared.global [%0], [%1], 16;" :: "r"(dst), "l"(src) : "memory");
}
__device__ __forceinline__ void cp_commit() {
    asm volatile("cp.async.commit_group;" ::: "memory");
}
template<int N>
__device__ __forceinline__ void cp_wait() {
    asm volatile("cp.async.wait_group %0;" :: "n"(N) : "memory");
}
__device__ __forceinline__ void ldsm_x4(uint32_t& r0, uint32_t& r1, uint32_t& r2, uint32_t& r3,
                                        uint32_t addr) {
    asm volatile("ldmatrix.sync.aligned.m8n8.x4.shared.b16 {%0,%1,%2,%3}, [%4];"
                 : "=r"(r0), "=r"(r1), "=r"(r2), "=r"(r3) : "r"(addr));
}
__device__ __forceinline__ void mma_fp16(float* c, uint32_t a0, uint32_t a1, uint32_t a2,
                                         uint32_t a3, uint32_t b0, uint32_t b1) {
    asm volatile("mma.sync.aligned.m16n8k16.row.col.f32.f16.f16.f32 "
                 "{%0,%1,%2,%3}, {%4,%5,%6,%7}, {%8,%9}, {%0,%1,%2,%3};"
                 : "+f"(c[0]), "+f"(c[1]), "+f"(c[2]), "+f"(c[3])
                 : "r"(a0), "r"(a1), "r"(a2), "r"(a3), "r"(b0), "r"(b1));
}

// ==================== weight transpose + split (once per launch) ====================
__global__ void wsplit_kernel(const float* __restrict__ W, __half* __restrict__ Th,
                              __half* __restrict__ Tl, int K, int N) {
    int i = blockIdx.x * blockDim.x + threadIdx.x;
    if (i >= K * N) return;
    int k = i / N, n = i % N;
    __half h, l;
    split_fp16(W[i], h, l);
    Th[(size_t)n * K + k] = h;
    Tl[(size_t)n * K + k] = l;
}

// ==================== fp16 split-2 GEMM (layers 1 & 2, tanh epilogue) ====================
// C = tanh(A @ (Wh+Wl)^T + bias); A: fp16 [M,K] K-major; W hi/lo: fp16 [N,K].
#define ROWB 144

template<int BM, int BN>
__global__ __launch_bounds__(256)
void gemm_mma(const __half* __restrict__ A,
              const __half* __restrict__ Bh, const __half* __restrict__ Bl,
              const float* __restrict__ bias,
              __half* __restrict__ C, int N, int K)
{
    constexpr int WR = BM / 32;
    constexpr int WC = 8 / WR;
    constexpr int WN = BN / WC;
    constexpr int NT = WN / 8;
    constexpr int BUF = (BM + 2 * BN) * ROWB;
    static_assert(WR * WC == 8, "warp layout");

    extern __shared__ char smem[];
    const uint32_t sbase = smem_u32(smem);

    const int tid = threadIdx.x, wid = tid >> 5, lane = tid & 31;
    const int wm = wid % WR, wn = wid / WR;
    const int rowBase = blockIdx.y * BM;
    const int colBase = blockIdx.x * BN;

    const uint32_t offA  = 0;
    const uint32_t offBh = (uint32_t)BM * ROWB;
    const uint32_t offBl = (uint32_t)(BM + BN) * ROWB;

    const int nchunks = K >> 6;

    auto load_chunk = [&](int c, int b) {
        const uint32_t stage = sbase + (uint32_t)b * BUF;
        const int kbase = c << 6;
        #pragma unroll
        for (int u = 0; u < BM * 8 / 256; u++) {
            int idx = tid + u * 256;
            int r = idx >> 3, q = idx & 7;
            size_t g = (size_t)(rowBase + r) * K + kbase + q * 8;
            uint32_t d = (uint32_t)(r * ROWB + q * 16);
            cp_async16(stage + offA + d, A + g);
        }
        #pragma unroll
        for (int u = 0; u < BN * 8 / 256; u++) {
            int idx = tid + u * 256;
            int r = idx >> 3, q = idx & 7;
            size_t g = (size_t)(colBase + r) * K + kbase + q * 8;
            uint32_t d = (uint32_t)(r * ROWB + q * 16);
            cp_async16(stage + offBh + d, Bh + g);
            cp_async16(stage + offBl + d, Bl + g);
        }
        cp_commit();
    };

    float acc[2][NT][4];
    #pragma unroll
    for (int mt = 0; mt < 2; mt++)
        #pragma unroll
        for (int nt = 0; nt < NT; nt++)
            #pragma unroll
            for (int j = 0; j < 4; j++)
                acc[mt][nt][j] = 0.0f;

    const int aRow = wm * 32 + (lane & 15);
    const int aByte = (lane & 16);
    const int bRow = wn * WN + ((lane & 16) >> 1) + (lane & 7);
    const int bByte = ((lane & 8) << 1);

    load_chunk(0, 0);

    for (int c = 0; c < nchunks; c++) {
        const int b = c & 1;
        if (c + 1 < nchunks) {
            load_chunk(c + 1, b ^ 1);
            cp_wait<1>();
        } else {
            cp_wait<0>();
        }
        __syncthreads();

        const uint32_t stage = sbase + (uint32_t)b * BUF;
        #pragma unroll
        for (int ks = 0; ks < 4; ks++) {
            uint32_t a[2][4];
            #pragma unroll
            for (int mt = 0; mt < 2; mt++) {
                uint32_t ad = stage + (uint32_t)((aRow + mt * 16) * ROWB + ks * 32 + aByte);
                ldsm_x4(a[mt][0], a[mt][1], a[mt][2], a[mt][3], ad + offA);
            }
            uint32_t bh[NT][2], bl[NT][2];
            #pragma unroll
            for (int nt2 = 0; nt2 < NT / 2; nt2++) {
                uint32_t bd = stage + (uint32_t)((bRow + nt2 * 16) * ROWB + ks * 32 + bByte);
                ldsm_x4(bh[nt2 * 2][0], bh[nt2 * 2][1], bh[nt2 * 2 + 1][0], bh[nt2 * 2 + 1][1],
                        bd + offBh);
                ldsm_x4(bl[nt2 * 2][0], bl[nt2 * 2][1], bl[nt2 * 2 + 1][0], bl[nt2 * 2 + 1][1],
                        bd + offBl);
            }
            #pragma unroll
            for (int mt = 0; mt < 2; mt++)
                #pragma unroll
                for (int nt = 0; nt < NT; nt++)
                    mma_fp16(acc[mt][nt], a[mt][0], a[mt][1], a[mt][2], a[mt][3],
                             bh[nt][0], bh[nt][1]);
            #pragma unroll
            for (int mt = 0; mt < 2; mt++)
                #pragma unroll
                for (int nt = 0; nt < NT; nt++)
                    mma_fp16(acc[mt][nt], a[mt][0], a[mt][1], a[mt][2], a[mt][3],
                             bl[nt][0], bl[nt][1]);
        }
        __syncthreads();
    }

    const int q = lane >> 2;
    const int p = lane & 3;
    #pragma unroll
    for (int mt = 0; mt < 2; mt++) {
        #pragma unroll
        for (int half = 0; half < 2; half++) {
            const int row = rowBase + wm * 32 + mt * 16 + q + half * 8;
            #pragma unroll
            for (int nt = 0; nt < NT; nt++) {
                const int col = colBase + wn * WN + nt * 8 + p * 2;
                float v0 = tanh_fast(acc[mt][nt][half * 2 + 0] + bias[col + 0]);
                float v1 = tanh_fast(acc[mt][nt][half * 2 + 1] + bias[col + 1]);
                *(__half2*)(C + (size_t)row * N + col) = __floats2half2_rn(v0, v1);
            }
        }
    }
}

// ==================== layer-3 GEMM with fused RK4 epilogue ====================
// EPI=1: k = acc+b3 -> kout (fp32); ytmp = y + coef*dt*k -> fp16 out.
// EPI=2: k4 = acc+b3; y_next = y + dt/6*(k1+2k2+2k3+k4) -> y, fp16 out, pred_y slice.
template<int EPI>
__global__ __launch_bounds__(256)
void gemm3_fused(const __half* __restrict__ A,
                 const __half* __restrict__ Bh, const __half* __restrict__ Bl,
                 const float* __restrict__ bias,
                 float* __restrict__ y,
                 float* __restrict__ kout,
                 const float* __restrict__ k1, const float* __restrict__ k2,
                 const float* __restrict__ k3,
                 __half* __restrict__ outq,
                 float* __restrict__ pred,
                 const float* __restrict__ t, int step, float coef,
                 int N, int K)
{
    constexpr int BM = 64, BN = 64;
    constexpr int WR = 2, WC = 4, WN = 16, NT = 2;
    constexpr int BUF = (BM + 2 * BN) * ROWB;

    extern __shared__ char smem[];
    const uint32_t sbase = smem_u32(smem);

    const int tid = threadIdx.x, wid = tid >> 5, lane = tid & 31;
    const int wm = wid % WR, wn = wid / WR;
    const int rowBase = blockIdx.y * BM;
    const int colBase = blockIdx.x * BN;

    const uint32_t offA  = 0;
    const uint32_t offBh = (uint32_t)BM * ROWB;
    const uint32_t offBl = (uint32_t)(BM + BN) * ROWB;

    const int nchunks = K >> 6;

    auto load_chunk = [&](int c, int b) {
        const uint32_t stage = sbase + (uint32_t)b * BUF;
        const int kbase = c << 6;
        #pragma unroll
        for (int u = 0; u < BM * 8 / 256; u++) {
            int idx = tid + u * 256;
            int r = idx >> 3, qq = idx & 7;
            size_t g = (size_t)(rowBase + r) * K + kbase + qq * 8;
            uint32_t d = (uint32_t)(r * ROWB + qq * 16);
            cp_async16(stage + offA + d, A + g);
        }
        #pragma unroll
        for (int u = 0; u < BN * 8 / 256; u++) {
            int idx = tid + u * 256;
            int r = idx >> 3, qq = idx & 7;
            size_t g = (size_t)(colBase + r) * K + kbase + qq * 8;
            uint32_t d = (uint32_t)(r * ROWB + qq * 16);
            cp_async16(stage + offBh + d, Bh + g);
            cp_async16(stage + offBl + d, Bl + g);
        }
        cp_commit();
    };

    float acc[2][NT][4];
    #pragma unroll
    for (int mt = 0; mt < 2; mt++)
        #pragma unroll
        for (int nt = 0; nt < NT; nt++)
            #pragma unroll
            for (int j = 0; j < 4; j++)
                acc[mt][nt][j] = 0.0f;

    const int aRow = wm * 32 + (lane & 15);
    const int aByte = (lane & 16);
    const int bRow = wn * WN + ((lane & 16) >> 1) + (lane & 7);
    const int bByte = ((lane & 8) << 1);

    load_chunk(0, 0);

    for (int c = 0; c < nchunks; c++) {
        const int b = c & 1;
        if (c + 1 < nchunks) {
            load_chunk(c + 1, b ^ 1);
            cp_wait<1>();
        } else {
            cp_wait<0>();
        }
        __syncthreads();

        const uint32_t stage = sbase + (uint32_t)b * BUF;
        #pragma unroll
        for (int ks = 0; ks < 4; ks++) {
            uint32_t a[2][4];
            #pragma unroll
            for (int mt = 0; mt < 2; mt++) {
                uint32_t ad = stage + (uint32_t)((aRow + mt * 16) * ROWB + ks * 32 + aByte);
                ldsm_x4(a[mt][0], a[mt][1], a[mt][2], a[mt][3], ad + offA);
            }
            uint32_t bh[NT][2], bl[NT][2];
            {
                uint32_t bd = stage + (uint32_t)(bRow * ROWB + ks * 32 + bByte);
                ldsm_x4(bh[0][0], bh[0][1], bh[1][0], bh[1][1], bd + offBh);
                ldsm_x4(bl[0][0], bl[0][1], bl[1][0], bl[1][1], bd + offBl);
            }
            #pragma unroll
            for (int mt = 0; mt < 2; mt++)
                #pragma unroll
                for (int nt = 0; nt < NT; nt++)
                    mma_fp16(acc[mt][nt], a[mt][0], a[mt][1], a[mt][2], a[mt][3],
                             bh[nt][0], bh[nt][1]);
            #pragma unroll
            for (int mt = 0; mt < 2; mt++)
                #pragma unroll
                for (int nt = 0; nt < NT; nt++)
                    mma_fp16(acc[mt][nt], a[mt][0], a[mt][1], a[mt][2], a[mt][3],
                             bl[nt][0], bl[nt][1]);
        }
        __syncthreads();
    }

    const float dtv = t[step + 1] - t[step];
    const float cax = coef * dtv;
    const float s6 = dtv * (1.0f / 6.0f);
    const int q = lane >> 2;
    const int p = lane & 3;
    #pragma unroll
    for (int mt = 0; mt < 2; mt++) {
        #pragma unroll
        for (int half = 0; half < 2; half++) {
            const int row = rowBase + wm * 32 + mt * 16 + q + half * 8;
            #pragma unroll
            for (int nt = 0; nt < NT; nt++) {
                const int col = colBase + wn * WN + nt * 8 + p * 2;
                const size_t gi = (size_t)row * N + col;
                float kv0 = acc[mt][nt][half * 2 + 0] + bias[col + 0];
                float kv1 = acc[mt][nt][half * 2 + 1] + bias[col + 1];
                if (EPI == 1) {
                    *(float2*)(kout + gi) = make_float2(kv0, kv1);
                    float2 yv = *(const float2*)(y + gi);
                    float o0 = fmaf(cax, kv0, yv.x);
                    float o1 = fmaf(cax, kv1, yv.y);
                    *(__half2*)(outq + gi) = __floats2half2_rn(o0, o1);
                } else {
                    float2 yv = *(const float2*)(y + gi);
                    float2 a1 = *(const float2*)(k1 + gi);
                    float2 a2 = *(const float2*)(k2 + gi);
                    float2 a3 = *(const float2*)(k3 + gi);
                    float o0 = yv.x + s6 * (a1.x + 2.0f * a2.x + 2.0f * a3.x + kv0);
                    float o1 = yv.y + s6 * (a1.y + 2.0f * a2.y + 2.0f * a3.y + kv1);
                    *(float2*)(y + gi) = make_float2(o0, o1);
                    *(__half2*)(outq + gi) = __floats2half2_rn(o0, o1);
                    *(float2*)(pred + ((size_t)row * TPTS + (step + 1)) * DDIM + col) =
                        make_float2(o0, o1);
                }
            }
        }
    }
}

// ==================== init ====================
__global__ void init_kernel(const float* __restrict__ fp, float* __restrict__ y,
                            __half* __restrict__ yq,
                            float* __restrict__ out, int out_size)
{
    const int i = blockIdx.x * blockDim.x + threadIdx.x;
    float4 v = reinterpret_cast<const float4*>(fp)[i];
    reinterpret_cast<float4*>(y)[i] = v;
    const int e = i * 4;
    *(__half2*)(yq + e + 0) = __floats2half2_rn(v.x, v.y);
    *(__half2*)(yq + e + 2) = __floats2half2_rn(v.z, v.w);
    const int row = e / DDIM;
    const int col = e % DDIM;
    *reinterpret_cast<float4*>(&out[(size_t)row * TPTS * DDIM + col]) = v;
    if (i == 0) {
        const int base = MROWS * TPTS * DDIM;
        for (int z = base; z < out_size; z++) out[z] = 0.0f;
    }
}

// ==================== launch ====================
#define SMEM_128 (2 * (128 + 2 * 128) * ROWB)    // 110592
#define SMEM_64  (2 * (64 + 2 * 64) * ROWB)      // 55296

extern "C" void kernel_launch(void* const* d_in, const int* in_sizes, int n_in,
                              void* d_out, int out_size)
{
    const float* fp = (const float*)d_in[0];
    const float* t  = (const float*)d_in[1];
    const float* W1 = (const float*)d_in[2];
    const float* b1 = (const float*)d_in[3];
    const float* W2 = (const float*)d_in[4];
    const float* b2 = (const float*)d_in[5];
    const float* W3 = (const float*)d_in[6];
    const float* b3 = (const float*)d_in[7];
    float* out = (float*)d_out;

    float *y, *k1, *k2, *k3;
    __half *yq, *ytq, *h1q, *h2q;
    __half *w1h, *w1l, *w2h, *w2l, *w3h, *w3l;
    cudaGetSymbolAddress((void**)&y,   g_y);
    cudaGetSymbolAddress((void**)&k1,  g_k1);
    cudaGetSymbolAddress((void**)&k2,  g_k2);
    cudaGetSymbolAddress((void**)&k3,  g_k3);
    cudaGetSymbolAddress((void**)&yq,  g_yq);
    cudaGetSymbolAddress((void**)&ytq, g_ytq);
    cudaGetSymbolAddress((void**)&h1q, g_h1q);
    cudaGetSymbolAddress((void**)&h2q, g_h2q);
    cudaGetSymbolAddress((void**)&w1h, g_w1h);
    cudaGetSymbolAddress((void**)&w1l, g_w1l);
    cudaGetSymbolAddress((void**)&w2h, g_w2h);
    cudaGetSymbolAddress((void**)&w2l, g_w2l);
    cudaGetSymbolAddress((void**)&w3h, g_w3h);
    cudaGetSymbolAddress((void**)&w3l, g_w3l);

    cudaFuncSetAttribute((const void*)gemm_mma<128, 128>,
                         cudaFuncAttributeMaxDynamicSharedMemorySize, SMEM_128);
    cudaFuncSetAttribute((const void*)gemm3_fused<1>,
                         cudaFuncAttributeMaxDynamicSharedMemorySize, SMEM_64);
    cudaFuncSetAttribute((const void*)gemm3_fused<2>,
                         cudaFuncAttributeMaxDynamicSharedMemorySize, SMEM_64);

    wsplit_kernel<<<(DDIM * HDIM + 255) / 256, 256>>>(W1, w1h, w1l, DDIM, HDIM);
    wsplit_kernel<<<(HDIM * HDIM + 255) / 256, 256>>>(W2, w2h, w2l, HDIM, HDIM);
    wsplit_kernel<<<(HDIM * DDIM + 255) / 256, 256>>>(W3, w3h, w3l, HDIM, DDIM);

    const int NV4 = (MROWS * DDIM) / 4;
    const dim3 ew_grid(NV4 / 256);
    init_kernel<<<ew_grid, 256>>>(fp, y, yq, out, out_size);

    const dim3 g12(HDIM / 128, MROWS / 128);
    const dim3 g3(DDIM / 64, MROWS / 64);

    auto mlp12 = [&](const __half* x) {
        gemm_mma<128, 128><<<g12, 256, SMEM_128>>>(x, w1h, w1l, b1, h1q, HDIM, DDIM);
        gemm_mma<128, 128><<<g12, 256, SMEM_128>>>(h1q, w2h, w2l, b2, h2q, HDIM, HDIM);
    };

    for (int s = 0; s < NSTEPS; s++) {
        mlp12(yq);
        gemm3_fused<1><<<g3, 256, SMEM_64>>>(h2q, w3h, w3l, b3, y, k1,
                                             nullptr, nullptr, nullptr,
                                             ytq, nullptr, t, s, 0.5f, DDIM, HDIM);
        mlp12(ytq);
        gemm3_fused<1><<<g3, 256, SMEM_64>>>(h2q, w3h, w3l, b3, y, k2,
                                             nullptr, nullptr, nullptr,
                                             ytq, nullptr, t, s, 0.5f, DDIM, HDIM);
        mlp12(ytq);
        gemm3_fused<1><<<g3, 256, SMEM_64>>>(h2q, w3h, w3l, b3, y, k3,
                                             nullptr, nullptr, nullptr,
                                             ytq, nullptr, t, s, 1.0f, DDIM, HDIM);
        mlp12(ytq);
        gemm3_fused<2><<<g3, 256, SMEM_64>>>(h2q, w3h, w3l, b3, y, nullptr,
                                             k1, k2, k3,
                                             yq, out, t, s, 0.0f, DDIM, HDIM);
    }
}

// round 8
// speedup vs baseline: 5.8398x; 1.4116x over previous
#include <cuda_runtime.h>
#include <cuda_fp16.h>
#include <cstdint>

// Problem dims: S=4, B=512 -> M=2048; D=256; H=1024; T=50 -> 49 RK4 steps
#define MROWS 2048
#define DDIM  256
#define HDIM  1024
#define TPTS  50
#define NSTEPS (TPTS - 1)

// ==================== device scratch ====================
__device__ float g_y [MROWS * DDIM];
__device__ float g_k1[MROWS * DDIM];
__device__ float g_k2[MROWS * DDIM];
__device__ float g_k3[MROWS * DDIM];
// fp16 activations
__device__ __half g_yq [MROWS * DDIM];
__device__ __half g_ytq[MROWS * DDIM];
__device__ __half g_h1q[MROWS * HDIM];
__device__ __half g_h2q[MROWS * HDIM];
// transposed fp16 weights: Wt[N][K]
__device__ __half g_w1[HDIM * DDIM];
__device__ __half g_w2[HDIM * HDIM];
__device__ __half g_w3[DDIM * HDIM];

// fast tanh: 1 - 2/(e^{2x}+1), via MUFU ex2 + rcp (abs err ~1e-7)
__device__ __forceinline__ float tanh_fast(float x) {
    float e;
    asm("ex2.approx.f32 %0, %1;" : "=f"(e) : "f"(x * 2.8853900817779268f));
    float r;
    asm("rcp.approx.f32 %0, %1;" : "=f"(r) : "f"(e + 1.0f));
    return fmaf(-2.0f, r, 1.0f);
}

__device__ __forceinline__ uint32_t smem_u32(const void* p) {
    uint32_t a;
    asm("{ .reg .u64 t; cvta.to.shared.u64 t, %1; cvt.u32.u64 %0, t; }" : "=r"(a) : "l"(p));
    return a;
}
__device__ __forceinline__ void cp_async16(uint32_t dst, const void* src) {
    asm volatile("cp.async.cg.shared.global [%0], [%1], 16;" :: "r"(dst), "l"(src) : "memory");
}
__device__ __forceinline__ void cp_commit() {
    asm volatile("cp.async.commit_group;" ::: "memory");
}
template<int N>
__device__ __forceinline__ void cp_wait() {
    asm volatile("cp.async.wait_group %0;" :: "n"(N) : "memory");
}
__device__ __forceinline__ void ldsm_x4(uint32_t& r0, uint32_t& r1, uint32_t& r2, uint32_t& r3,
                                        uint32_t addr) {
    asm volatile("ldmatrix.sync.aligned.m8n8.x4.shared.b16 {%0,%1,%2,%3}, [%4];"
                 : "=r"(r0), "=r"(r1), "=r"(r2), "=r"(r3) : "r"(addr));
}
__device__ __forceinline__ void mma_fp16(float* c, uint32_t a0, uint32_t a1, uint32_t a2,
                                         uint32_t a3, uint32_t b0, uint32_t b1) {
    asm volatile("mma.sync.aligned.m16n8k16.row.col.f32.f16.f16.f32 "
                 "{%0,%1,%2,%3}, {%4,%5,%6,%7}, {%8,%9}, {%0,%1,%2,%3};"
                 : "+f"(c[0]), "+f"(c[1]), "+f"(c[2]), "+f"(c[3])
                 : "r"(a0), "r"(a1), "r"(a2), "r"(a3), "r"(b0), "r"(b1));
}

// ==================== weight transpose (once per launch) ====================
__global__ void wsplit_kernel(const float* __restrict__ W, __half* __restrict__ T,
                              int K, int N) {
    int i = blockIdx.x * blockDim.x + threadIdx.x;
    if (i >= K * N) return;
    int k = i / N, n = i % N;
    T[(size_t)n * K + k] = __float2half(W[i]);
}

// ==================== fp16 GEMM (layers 1 & 2, tanh epilogue) ====================
// C = tanh(A @ W^T + bias); A: fp16 [M,K] K-major; W: fp16 [N,K].
#define ROWB 144

template<int BM, int BN>
__global__ __launch_bounds__(256)
void gemm_mma(const __half* __restrict__ A,
              const __half* __restrict__ B,
              const float* __restrict__ bias,
              __half* __restrict__ C, int N, int K)
{
    constexpr int WR = BM / 32;
    constexpr int WC = 8 / WR;
    constexpr int WN = BN / WC;
    constexpr int NT = WN / 8;
    constexpr int BUF = (BM + BN) * ROWB;
    static_assert(WR * WC == 8, "warp layout");

    extern __shared__ char smem[];
    const uint32_t sbase = smem_u32(smem);

    const int tid = threadIdx.x, wid = tid >> 5, lane = tid & 31;
    const int wm = wid % WR, wn = wid / WR;
    const int rowBase = blockIdx.y * BM;
    const int colBase = blockIdx.x * BN;

    const uint32_t offA = 0;
    const uint32_t offB = (uint32_t)BM * ROWB;

    const int nchunks = K >> 6;

    auto load_chunk = [&](int c, int b) {
        const uint32_t stage = sbase + (uint32_t)b * BUF;
        const int kbase = c << 6;
        #pragma unroll
        for (int u = 0; u < BM * 8 / 256; u++) {
            int idx = tid + u * 256;
            int r = idx >> 3, q = idx & 7;
            size_t g = (size_t)(rowBase + r) * K + kbase + q * 8;
            cp_async16(stage + offA + (uint32_t)(r * ROWB + q * 16), A + g);
        }
        #pragma unroll
        for (int u = 0; u < BN * 8 / 256; u++) {
            int idx = tid + u * 256;
            int r = idx >> 3, q = idx & 7;
            size_t g = (size_t)(colBase + r) * K + kbase + q * 8;
            cp_async16(stage + offB + (uint32_t)(r * ROWB + q * 16), B + g);
        }
        cp_commit();
    };

    float acc[2][NT][4];
    #pragma unroll
    for (int mt = 0; mt < 2; mt++)
        #pragma unroll
        for (int nt = 0; nt < NT; nt++)
            #pragma unroll
            for (int j = 0; j < 4; j++)
                acc[mt][nt][j] = 0.0f;

    const int aRow = wm * 32 + (lane & 15);
    const int aByte = (lane & 16);
    const int bRow = wn * WN + ((lane & 16) >> 1) + (lane & 7);
    const int bByte = ((lane & 8) << 1);

    load_chunk(0, 0);

    for (int c = 0; c < nchunks; c++) {
        const int b = c & 1;
        if (c + 1 < nchunks) {
            load_chunk(c + 1, b ^ 1);
            cp_wait<1>();
        } else {
            cp_wait<0>();
        }
        __syncthreads();

        const uint32_t stage = sbase + (uint32_t)b * BUF;
        #pragma unroll
        for (int ks = 0; ks < 4; ks++) {
            uint32_t a[2][4];
            #pragma unroll
            for (int mt = 0; mt < 2; mt++) {
                uint32_t ad = stage + (uint32_t)((aRow + mt * 16) * ROWB + ks * 32 + aByte);
                ldsm_x4(a[mt][0], a[mt][1], a[mt][2], a[mt][3], ad + offA);
            }
            uint32_t bb[NT][2];
            #pragma unroll
            for (int nt2 = 0; nt2 < NT / 2; nt2++) {
                uint32_t bd = stage + (uint32_t)((bRow + nt2 * 16) * ROWB + ks * 32 + bByte);
                ldsm_x4(bb[nt2 * 2][0], bb[nt2 * 2][1], bb[nt2 * 2 + 1][0], bb[nt2 * 2 + 1][1],
                        bd + offB);
            }
            #pragma unroll
            for (int mt = 0; mt < 2; mt++)
                #pragma unroll
                for (int nt = 0; nt < NT; nt++)
                    mma_fp16(acc[mt][nt], a[mt][0], a[mt][1], a[mt][2], a[mt][3],
                             bb[nt][0], bb[nt][1]);
        }
        __syncthreads();
    }

    const int q = lane >> 2;
    const int p = lane & 3;
    #pragma unroll
    for (int mt = 0; mt < 2; mt++) {
        #pragma unroll
        for (int half = 0; half < 2; half++) {
            const int row = rowBase + wm * 32 + mt * 16 + q + half * 8;
            #pragma unroll
            for (int nt = 0; nt < NT; nt++) {
                const int col = colBase + wn * WN + nt * 8 + p * 2;
                float v0 = tanh_fast(acc[mt][nt][half * 2 + 0] + bias[col + 0]);
                float v1 = tanh_fast(acc[mt][nt][half * 2 + 1] + bias[col + 1]);
                *(__half2*)(C + (size_t)row * N + col) = __floats2half2_rn(v0, v1);
            }
        }
    }
}

// ==================== layer-3 GEMM with fused RK4 epilogue ====================
// EPI=1: k = acc+b3 -> kout (fp32); ytmp = y + coef*dt*k -> fp16 out.
// EPI=2: k4 = acc+b3; y_next = y + dt/6*(k1+2k2+2k3+k4) -> y, fp16 out, pred_y slice.
template<int EPI>
__global__ __launch_bounds__(256)
void gemm3_fused(const __half* __restrict__ A,
                 const __half* __restrict__ B,
                 const float* __restrict__ bias,
                 float* __restrict__ y,
                 float* __restrict__ kout,
                 const float* __restrict__ k1, const float* __restrict__ k2,
                 const float* __restrict__ k3,
                 __half* __restrict__ outq,
                 float* __restrict__ pred,
                 const float* __restrict__ t, int step, float coef,
                 int N, int K)
{
    constexpr int BM = 64, BN = 64;
    constexpr int WR = 2, WC = 4, WN = 16, NT = 2;
    constexpr int BUF = (BM + BN) * ROWB;

    extern __shared__ char smem[];
    const uint32_t sbase = smem_u32(smem);

    const int tid = threadIdx.x, wid = tid >> 5, lane = tid & 31;
    const int wm = wid % WR, wn = wid / WR;
    const int rowBase = blockIdx.y * BM;
    const int colBase = blockIdx.x * BN;

    const uint32_t offA = 0;
    const uint32_t offB = (uint32_t)BM * ROWB;

    const int nchunks = K >> 6;

    auto load_chunk = [&](int c, int b) {
        const uint32_t stage = sbase + (uint32_t)b * BUF;
        const int kbase = c << 6;
        #pragma unroll
        for (int u = 0; u < BM * 8 / 256; u++) {
            int idx = tid + u * 256;
            int r = idx >> 3, qq = idx & 7;
            size_t g = (size_t)(rowBase + r) * K + kbase + qq * 8;
            cp_async16(stage + offA + (uint32_t)(r * ROWB + qq * 16), A + g);
        }
        #pragma unroll
        for (int u = 0; u < BN * 8 / 256; u++) {
            int idx = tid + u * 256;
            int r = idx >> 3, qq = idx & 7;
            size_t g = (size_t)(colBase + r) * K + kbase + qq * 8;
            cp_async16(stage + offB + (uint32_t)(r * ROWB + qq * 16), B + g);
        }
        cp_commit();
    };

    float acc[2][NT][4];
    #pragma unroll
    for (int mt = 0; mt < 2; mt++)
        #pragma unroll
        for (int nt = 0; nt < NT; nt++)
            #pragma unroll
            for (int j = 0; j < 4; j++)
                acc[mt][nt][j] = 0.0f;

    const int aRow = wm * 32 + (lane & 15);
    const int aByte = (lane & 16);
    const int bRow = wn * WN + ((lane & 16) >> 1) + (lane & 7);
    const int bByte = ((lane & 8) << 1);

    load_chunk(0, 0);

    for (int c = 0; c < nchunks; c++) {
        const int b = c & 1;
        if (c + 1 < nchunks) {
            load_chunk(c + 1, b ^ 1);
            cp_wait<1>();
        } else {
            cp_wait<0>();
        }
        __syncthreads();

        const uint32_t stage = sbase + (uint32_t)b * BUF;
        #pragma unroll
        for (int ks = 0; ks < 4; ks++) {
            uint32_t a[2][4];
            #pragma unroll
            for (int mt = 0; mt < 2; mt++) {
                uint32_t ad = stage + (uint32_t)((aRow + mt * 16) * ROWB + ks * 32 + aByte);
                ldsm_x4(a[mt][0], a[mt][1], a[mt][2], a[mt][3], ad + offA);
            }
            uint32_t bb[NT][2];
            {
                uint32_t bd = stage + (uint32_t)(bRow * ROWB + ks * 32 + bByte);
                ldsm_x4(bb[0][0], bb[0][1], bb[1][0], bb[1][1], bd + offB);
            }
            #pragma unroll
            for (int mt = 0; mt < 2; mt++)
                #pragma unroll
                for (int nt = 0; nt < NT; nt++)
                    mma_fp16(acc[mt][nt], a[mt][0], a[mt][1], a[mt][2], a[mt][3],
                             bb[nt][0], bb[nt][1]);
        }
        __syncthreads();
    }

    const float dtv = t[step + 1] - t[step];
    const float cax = coef * dtv;
    const float s6 = dtv * (1.0f / 6.0f);
    const int q = lane >> 2;
    const int p = lane & 3;
    #pragma unroll
    for (int mt = 0; mt < 2; mt++) {
        #pragma unroll
        for (int half = 0; half < 2; half++) {
            const int row = rowBase + wm * 32 + mt * 16 + q + half * 8;
            #pragma unroll
            for (int nt = 0; nt < NT; nt++) {
                const int col = colBase + wn * WN + nt * 8 + p * 2;
                const size_t gi = (size_t)row * N + col;
                float kv0 = acc[mt][nt][half * 2 + 0] + bias[col + 0];
                float kv1 = acc[mt][nt][half * 2 + 1] + bias[col + 1];
                if (EPI == 1) {
                    *(float2*)(kout + gi) = make_float2(kv0, kv1);
                    float2 yv = *(const float2*)(y + gi);
                    float o0 = fmaf(cax, kv0, yv.x);
                    float o1 = fmaf(cax, kv1, yv.y);
                    *(__half2*)(outq + gi) = __floats2half2_rn(o0, o1);
                } else {
                    float2 yv = *(const float2*)(y + gi);
                    float2 a1 = *(const float2*)(k1 + gi);
                    float2 a2 = *(const float2*)(k2 + gi);
                    float2 a3 = *(const float2*)(k3 + gi);
                    float o0 = yv.x + s6 * (a1.x + 2.0f * a2.x + 2.0f * a3.x + kv0);
                    float o1 = yv.y + s6 * (a1.y + 2.0f * a2.y + 2.0f * a3.y + kv1);
                    *(float2*)(y + gi) = make_float2(o0, o1);
                    *(__half2*)(outq + gi) = __floats2half2_rn(o0, o1);
                    *(float2*)(pred + ((size_t)row * TPTS + (step + 1)) * DDIM + col) =
                        make_float2(o0, o1);
                }
            }
        }
    }
}

// ==================== init ====================
__global__ void init_kernel(const float* __restrict__ fp, float* __restrict__ y,
                            __half* __restrict__ yq,
                            float* __restrict__ out, int out_size)
{
    const int i = blockIdx.x * blockDim.x + threadIdx.x;
    float4 v = reinterpret_cast<const float4*>(fp)[i];
    reinterpret_cast<float4*>(y)[i] = v;
    const int e = i * 4;
    *(__half2*)(yq + e + 0) = __floats2half2_rn(v.x, v.y);
    *(__half2*)(yq + e + 2) = __floats2half2_rn(v.z, v.w);
    const int row = e / DDIM;
    const int col = e % DDIM;
    *reinterpret_cast<float4*>(&out[(size_t)row * TPTS * DDIM + col]) = v;
    if (i == 0) {
        const int base = MROWS * TPTS * DDIM;
        for (int z = base; z < out_size; z++) out[z] = 0.0f;
    }
}

// ==================== launch ====================
#define SMEM_128 (2 * (128 + 128) * ROWB)    // 73728
#define SMEM_64  (2 * (64 + 64) * ROWB)      // 36864

extern "C" void kernel_launch(void* const* d_in, const int* in_sizes, int n_in,
                              void* d_out, int out_size)
{
    const float* fp = (const float*)d_in[0];
    const float* t  = (const float*)d_in[1];
    const float* W1 = (const float*)d_in[2];
    const float* b1 = (const float*)d_in[3];
    const float* W2 = (const float*)d_in[4];
    const float* b2 = (const float*)d_in[5];
    const float* W3 = (const float*)d_in[6];
    const float* b3 = (const float*)d_in[7];
    float* out = (float*)d_out;

    float *y, *k1, *k2, *k3;
    __half *yq, *ytq, *h1q, *h2q, *w1, *w2, *w3;
    cudaGetSymbolAddress((void**)&y,   g_y);
    cudaGetSymbolAddress((void**)&k1,  g_k1);
    cudaGetSymbolAddress((void**)&k2,  g_k2);
    cudaGetSymbolAddress((void**)&k3,  g_k3);
    cudaGetSymbolAddress((void**)&yq,  g_yq);
    cudaGetSymbolAddress((void**)&ytq, g_ytq);
    cudaGetSymbolAddress((void**)&h1q, g_h1q);
    cudaGetSymbolAddress((void**)&h2q, g_h2q);
    cudaGetSymbolAddress((void**)&w1,  g_w1);
    cudaGetSymbolAddress((void**)&w2,  g_w2);
    cudaGetSymbolAddress((void**)&w3,  g_w3);

    cudaFuncSetAttribute((const void*)gemm_mma<128, 128>,
                         cudaFuncAttributeMaxDynamicSharedMemorySize, SMEM_128);
    cudaFuncSetAttribute((const void*)gemm3_fused<1>,
                         cudaFuncAttributeMaxDynamicSharedMemorySize, SMEM_64);
    cudaFuncSetAttribute((const void*)gemm3_fused<2>,
                         cudaFuncAttributeMaxDynamicSharedMemorySize, SMEM_64);

    wsplit_kernel<<<(DDIM * HDIM + 255) / 256, 256>>>(W1, w1, DDIM, HDIM);
    wsplit_kernel<<<(HDIM * HDIM + 255) / 256, 256>>>(W2, w2, HDIM, HDIM);
    wsplit_kernel<<<(HDIM * DDIM + 255) / 256, 256>>>(W3, w3, HDIM, DDIM);

    const int NV4 = (MROWS * DDIM) / 4;
    const dim3 ew_grid(NV4 / 256);
    init_kernel<<<ew_grid, 256>>>(fp, y, yq, out, out_size);

    const dim3 g12(HDIM / 128, MROWS / 128);
    const dim3 g3(DDIM / 64, MROWS / 64);

    auto mlp12 = [&](const __half* x) {
        gemm_mma<128, 128><<<g12, 256, SMEM_128>>>(x, w1, b1, h1q, HDIM, DDIM);
        gemm_mma<128, 128><<<g12, 256, SMEM_128>>>(h1q, w2, b2, h2q, HDIM, HDIM);
    };

    for (int s = 0; s < NSTEPS; s++) {
        mlp12(yq);
        gemm3_fused<1><<<g3, 256, SMEM_64>>>(h2q, w3, b3, y, k1,
                                             nullptr, nullptr, nullptr,
                                             ytq, nullptr, t, s, 0.5f, DDIM, HDIM);
        mlp12(ytq);
        gemm3_fused<1><<<g3, 256, SMEM_64>>>(h2q, w3, b3, y, k2,
                                             nullptr, nullptr, nullptr,
                                             ytq, nullptr, t, s, 0.5f, DDIM, HDIM);
        mlp12(ytq);
        gemm3_fused<1><<<g3, 256, SMEM_64>>>(h2q, w3, b3, y, k3,
                                             nullptr, nullptr, nullptr,
                                             ytq, nullptr, t, s, 1.0f, DDIM, HDIM);
        mlp12(ytq);
        gemm3_fused<2><<<g3, 256, SMEM_64>>>(h2q, w3, b3, y, nullptr,
                                             k1, k2, k3,
                                             yq, out, t, s, 0.0f, DDIM, HDIM);
    }
}